// round 5
// baseline (speedup 1.0000x reference)
#include <cuda_runtime.h>
#include <cuda_bf16.h>
#include <cstdint>

// Problem constants
#define BATCH 2
#define SEQ   2048
#define DIM   1024
#define NH    16
#define HD    64
#define MROWS (BATCH*SEQ)          // 4096
#define QKV_N (3*DIM)              // 3072

// Scratch (device globals; no allocation allowed)
__device__ float g_q[BATCH*NH*SEQ*HD];   // [b][h][s][d], pre-scaled by 1/sqrt(HD)
__device__ float g_k[BATCH*NH*SEQ*HD];   // [b][h][s][d]
__device__ float g_vt[BATCH*NH*HD*SEQ];  // [b][h][d][s]  (transposed V)
__device__ float g_ao[BATCH*SEQ*DIM];    // attention output, [b][s][h*64+d]

__device__ __forceinline__ uint32_t f2tf(float x) {
    uint32_t y;
    asm("cvt.rna.tf32.f32 %0, %1;" : "=r"(y) : "f"(x));
    return y;
}

__device__ __forceinline__ void mma_tf32(float (&d)[4],
                                         const uint32_t (&a)[4],
                                         const uint32_t (&b)[2]) {
    asm volatile(
        "mma.sync.aligned.m16n8k8.row.col.f32.tf32.tf32.f32 "
        "{%0,%1,%2,%3}, {%4,%5,%6,%7}, {%8,%9}, {%0,%1,%2,%3};"
        : "+f"(d[0]), "+f"(d[1]), "+f"(d[2]), "+f"(d[3])
        : "r"(a[0]), "r"(a[1]), "r"(a[2]), "r"(a[3]), "r"(b[0]), "r"(b[1]));
}

// ---------------------------------------------------------------------------
// tf32 tensor-core GEMM: CTA tile 128x128x32, 8 warps (2m x 4n), warp 64x32.
// A row-major As [m][k], B transposed in smem Bs [n][k]; all frags via ldmatrix.
// ---------------------------------------------------------------------------
#define GBM 128
#define GBN 128
#define GBK 32
#define AS_STRIDE 36
#define BS_STRIDE 36

__device__ __forceinline__ void gemm_tile_tf32(const float* __restrict__ A,
                                               const float* __restrict__ B,
                                               const int N,
                                               float (&acc)[4][4][4]) {
    __shared__ __align__(16) float As[GBM * AS_STRIDE];
    __shared__ __align__(16) float Bs[GBN * BS_STRIDE];

    const int K = DIM;
    const int tid = threadIdx.x;
    const int lane = tid & 31;
    const int w = tid >> 5;
    const int warpM = (w & 1) * 64;
    const int warpN = (w >> 1) * 32;

    const float* Ag = A + (size_t)(blockIdx.y * GBM) * K;
    const float* Bg = B + blockIdx.x * GBN;

    const int sub = lane >> 3, r8 = lane & 7;
    // A-frag lane offset (row-major As)
    const uint32_t lofA = (uint32_t)((((sub & 1) * 8 + r8) * AS_STRIDE) * 4 + (sub >> 1) * 16);
    // B-frag lane layout on n-major Bs (chunk pair x 8 rows), proven in attn_tc
    const int brow = (sub >> 1) * 8 + r8;
    const int bchunk = (sub & 1) * 16;
    const uint32_t as_base = (uint32_t)__cvta_generic_to_shared(As);
    const uint32_t bs_base = (uint32_t)__cvta_generic_to_shared(Bs);

    const int a_row = tid >> 3;
    const int a_k4  = (tid & 7) * 4;
    const int b_k   = tid >> 5;        // 0..7 (+ it*8)
    const int b_n4  = (tid & 31) * 4;  // n offset

    float4 pa[4], pb[4];
    #pragma unroll
    for (int it = 0; it < 4; it++) {
        pa[it] = *(const float4*)(Ag + (size_t)(a_row + it * 32) * K + a_k4);
        pb[it] = *(const float4*)(Bg + (size_t)(b_k + it * 8) * N + b_n4);
    }

    const int NKT = K / GBK;
    for (int kt = 0; kt < NKT; kt++) {
        #pragma unroll
        for (int it = 0; it < 4; it++) {
            float4 v = pa[it], c;
            c.x = __uint_as_float(f2tf(v.x));
            c.y = __uint_as_float(f2tf(v.y));
            c.z = __uint_as_float(f2tf(v.z));
            c.w = __uint_as_float(f2tf(v.w));
            *(float4*)&As[(a_row + it * 32) * AS_STRIDE + a_k4] = c;
            // B: transpose into Bs[n][k]
            float4 u = pb[it];
            int kk = b_k + it * 8;
            Bs[(b_n4 + 0) * BS_STRIDE + kk] = __uint_as_float(f2tf(u.x));
            Bs[(b_n4 + 1) * BS_STRIDE + kk] = __uint_as_float(f2tf(u.y));
            Bs[(b_n4 + 2) * BS_STRIDE + kk] = __uint_as_float(f2tf(u.z));
            Bs[(b_n4 + 3) * BS_STRIDE + kk] = __uint_as_float(f2tf(u.w));
        }
        __syncthreads();

        if (kt + 1 < NKT) {
            const float* Ag2 = Ag + (kt + 1) * GBK;
            const float* Bg2 = Bg + (size_t)(kt + 1) * GBK * N;
            #pragma unroll
            for (int it = 0; it < 4; it++) {
                pa[it] = *(const float4*)(Ag2 + (size_t)(a_row + it * 32) * K + a_k4);
                pb[it] = *(const float4*)(Bg2 + (size_t)(b_k + it * 8) * N + b_n4);
            }
        }

        #pragma unroll
        for (int ks = 0; ks < 4; ks++) {
            uint32_t af[4][4];
            #pragma unroll
            for (int mt = 0; mt < 4; mt++) {
                uint32_t addr = as_base
                              + (uint32_t)(((warpM + mt * 16) * AS_STRIDE) * 4 + ks * 32)
                              + lofA;
                asm volatile(
                    "ldmatrix.sync.aligned.m8n8.x4.shared.b16 {%0,%1,%2,%3}, [%4];"
                    : "=r"(af[mt][0]), "=r"(af[mt][1]), "=r"(af[mt][2]), "=r"(af[mt][3])
                    : "r"(addr));
            }
            uint32_t bf[4][2];
            #pragma unroll
            for (int p = 0; p < 2; p++) {
                uint32_t bq[4];
                uint32_t baddr = bs_base
                               + (uint32_t)(((warpN + p * 16 + brow) * BS_STRIDE) * 4
                                            + ks * 32 + bchunk);
                asm volatile(
                    "ldmatrix.sync.aligned.m8n8.x4.shared.b16 {%0,%1,%2,%3}, [%4];"
                    : "=r"(bq[0]), "=r"(bq[1]), "=r"(bq[2]), "=r"(bq[3]) : "r"(baddr));
                bf[2 * p][0]     = bq[0];
                bf[2 * p][1]     = bq[1];
                bf[2 * p + 1][0] = bq[2];
                bf[2 * p + 1][1] = bq[3];
            }
            #pragma unroll
            for (int mt = 0; mt < 4; mt++)
                #pragma unroll
                for (int nt = 0; nt < 4; nt++)
                    mma_tf32(acc[mt][nt], af[mt], bf[nt]);
        }
        __syncthreads();
    }
}

__global__ __launch_bounds__(256) void gemm_qkv_tc(const float* __restrict__ A,
                                                   const float* __restrict__ B,
                                                   const float* __restrict__ bias) {
    float acc[4][4][4];
    #pragma unroll
    for (int i = 0; i < 4; i++)
        #pragma unroll
        for (int j = 0; j < 4; j++)
            #pragma unroll
            for (int k = 0; k < 4; k++) acc[i][j][k] = 0.f;

    gemm_tile_tf32(A, B, QKV_N, acc);

    const int tid = threadIdx.x;
    const int lane = tid & 31;
    const int w = tid >> 5;
    const int warpM = (w & 1) * 64;
    const int warpN = (w >> 1) * 32;
    const int g = lane >> 2, t = lane & 3;

    #pragma unroll
    for (int mt = 0; mt < 4; mt++) {
        #pragma unroll
        for (int nt = 0; nt < 4; nt++) {
            int col = blockIdx.x * GBN + warpN + nt * 8 + t * 2;
            float b0 = bias[col], b1 = bias[col + 1];
            int part = col >> 10;
            int h = (col >> 6) & (NH - 1);
            int d = col & (HD - 1);
            #pragma unroll
            for (int half = 0; half < 2; half++) {
                int r = blockIdx.y * GBM + warpM + mt * 16 + g + half * 8;
                int b_ = r >> 11, s = r & (SEQ - 1);
                float v0 = acc[mt][nt][half * 2 + 0] + b0;
                float v1 = acc[mt][nt][half * 2 + 1] + b1;
                if (part == 0) {
                    int idx = (((b_ * NH + h) * SEQ) + s) * HD + d;
                    g_q[idx] = v0 * 0.125f;
                    g_q[idx + 1] = v1 * 0.125f;
                } else if (part == 1) {
                    int idx = (((b_ * NH + h) * SEQ) + s) * HD + d;
                    g_k[idx] = v0; g_k[idx + 1] = v1;
                } else {
                    size_t vb = ((size_t)(b_ * NH + h) * HD + d) * SEQ + s;
                    g_vt[vb] = v0;
                    g_vt[vb + SEQ] = v1;
                }
            }
        }
    }
}

__global__ __launch_bounds__(256) void gemm_out_tc(const float* __restrict__ B,
                                                   const float* __restrict__ bias,
                                                   float* __restrict__ C) {
    float acc[4][4][4];
    #pragma unroll
    for (int i = 0; i < 4; i++)
        #pragma unroll
        for (int j = 0; j < 4; j++)
            #pragma unroll
            for (int k = 0; k < 4; k++) acc[i][j][k] = 0.f;

    gemm_tile_tf32(g_ao, B, DIM, acc);

    const int tid = threadIdx.x;
    const int lane = tid & 31;
    const int w = tid >> 5;
    const int warpM = (w & 1) * 64;
    const int warpN = (w >> 1) * 32;
    const int g = lane >> 2, t = lane & 3;

    #pragma unroll
    for (int mt = 0; mt < 4; mt++) {
        #pragma unroll
        for (int nt = 0; nt < 4; nt++) {
            int col = blockIdx.x * GBN + warpN + nt * 8 + t * 2;
            float b0 = bias[col], b1 = bias[col + 1];
            #pragma unroll
            for (int half = 0; half < 2; half++) {
                int r = blockIdx.y * GBM + warpM + mt * 16 + g + half * 8;
                float2 o;
                o.x = acc[mt][nt][half * 2 + 0] + b0;
                o.y = acc[mt][nt][half * 2 + 1] + b1;
                *(float2*)(C + (size_t)r * DIM + col) = o;
            }
        }
    }
}

// ---------------------------------------------------------------------------
// Tensor-core causal flash attention (tf32 mma), all fragments via ldmatrix.
// CTA: 128 q-rows x 64 kv per tile, 8 warps x 16 q-rows, Hd=64.
// PV A-fragments redistributed from S-accumulators via quad shfl (no Ps smem).
// grid = (16 q-tiles, 32 b*h); longest q-tiles scheduled first.
// ---------------------------------------------------------------------------
#define ATQ 128
#define ATK 64
#define QS_S 68
#define KS_S 68
#define VT_S 68
#define ATTN_SMEM ((ATQ*QS_S + ATK*KS_S + HD*VT_S) * 4)

__global__ __launch_bounds__(256, 2) void attn_tc() {
    extern __shared__ float sm[];
    float* Qs = sm;                     // [128][68]  (q, d)
    float* Ks = Qs + ATQ * QS_S;        // [64][68]   (kv, d)
    float* Vt = Ks + ATK * KS_S;        // [64][68]   (d, kv)

    const int tid = threadIdx.x;
    const int lane = tid & 31;
    const int wp = tid >> 5;
    const int g = lane >> 2, t = lane & 3;

    const int qt = (gridDim.x - 1) - blockIdx.x;   // longest first
    const int bh = blockIdx.y;
    const int q0 = qt * ATQ;
    const float* Qp  = g_q  + (size_t)bh * SEQ * HD;
    const float* Kp  = g_k  + (size_t)bh * SEQ * HD;
    const float* Vtp = g_vt + (size_t)bh * HD * SEQ;

    const int sub = lane >> 3, r8 = lane & 7;
    const uint32_t lofQ = (uint32_t)((((sub & 1) * 8 + r8) * QS_S) * 4 + (sub >> 1) * 16);
    const int brow = (sub >> 1) * 8 + r8;
    const int bchunk = (sub & 1) * 16;
    const uint32_t qs_base = (uint32_t)__cvta_generic_to_shared(Qs);
    const uint32_t ks_base = (uint32_t)__cvta_generic_to_shared(Ks);
    const uint32_t vt_base = (uint32_t)__cvta_generic_to_shared(Vt);

    for (int i = tid; i < ATQ * (HD / 4); i += 256) {
        int r = i >> 4, c4 = (i & 15) * 4;
        float4 v = *(const float4*)(Qp + (size_t)(q0 + r) * HD + c4);
        float4 c;
        c.x = __uint_as_float(f2tf(v.x));
        c.y = __uint_as_float(f2tf(v.y));
        c.z = __uint_as_float(f2tf(v.z));
        c.w = __uint_as_float(f2tf(v.w));
        *(float4*)&Qs[r * QS_S + c4] = c;
    }

    float o[8][4];
    #pragma unroll
    for (int nt = 0; nt < 8; nt++)
        #pragma unroll
        for (int c = 0; c < 4; c++) o[nt][c] = 0.f;
    float m0 = -1e30f, m1 = -1e30f, l0 = 0.f, l1 = 0.f;

    const int srcA = (lane & ~3) | (t >> 1);
    const int srcB = srcA + 2;

    const int ntiles = 2 * qt + 2;
    for (int jt = 0; jt < ntiles; jt++) {
        if (jt) __syncthreads();
        const int kv0 = jt * ATK;
        for (int i = tid; i < ATK * (HD / 4); i += 256) {
            int r = i >> 4, c4 = (i & 15) * 4;
            float4 kk = *(const float4*)(Kp + (size_t)(kv0 + r) * HD + c4);
            float4 ck;
            ck.x = __uint_as_float(f2tf(kk.x));
            ck.y = __uint_as_float(f2tf(kk.y));
            ck.z = __uint_as_float(f2tf(kk.z));
            ck.w = __uint_as_float(f2tf(kk.w));
            *(float4*)&Ks[r * KS_S + c4] = ck;
            float4 vv = *(const float4*)(Vtp + (size_t)r * SEQ + kv0 + c4);
            float4 cv;
            cv.x = __uint_as_float(f2tf(vv.x));
            cv.y = __uint_as_float(f2tf(vv.y));
            cv.z = __uint_as_float(f2tf(vv.z));
            cv.w = __uint_as_float(f2tf(vv.w));
            *(float4*)&Vt[r * VT_S + c4] = cv;
        }
        __syncthreads();

        float s[8][4];
        #pragma unroll
        for (int nt = 0; nt < 8; nt++)
            #pragma unroll
            for (int c = 0; c < 4; c++) s[nt][c] = 0.f;

        #pragma unroll
        for (int ks = 0; ks < 8; ks++) {
            uint32_t a[4];
            uint32_t addr = qs_base
                          + (uint32_t)(((wp * 16) * QS_S) * 4 + ks * 32) + lofQ;
            asm volatile(
                "ldmatrix.sync.aligned.m8n8.x4.shared.b16 {%0,%1,%2,%3}, [%4];"
                : "=r"(a[0]), "=r"(a[1]), "=r"(a[2]), "=r"(a[3]) : "r"(addr));
            #pragma unroll
            for (int p = 0; p < 4; p++) {
                uint32_t bq[4];
                uint32_t baddr = ks_base
                               + (uint32_t)(((p * 16 + brow) * KS_S) * 4 + ks * 32 + bchunk);
                asm volatile(
                    "ldmatrix.sync.aligned.m8n8.x4.shared.b16 {%0,%1,%2,%3}, [%4];"
                    : "=r"(bq[0]), "=r"(bq[1]), "=r"(bq[2]), "=r"(bq[3]) : "r"(baddr));
                uint32_t b0[2] = {bq[0], bq[1]};
                uint32_t b1[2] = {bq[2], bq[3]};
                mma_tf32(s[2 * p], a, b0);
                mma_tf32(s[2 * p + 1], a, b1);
            }
        }

        if (jt >= 2 * qt) {
            int r0 = q0 + wp * 16 + g, r1 = r0 + 8;
            #pragma unroll
            for (int nt = 0; nt < 8; nt++) {
                int c0 = kv0 + nt * 8 + 2 * t;
                if (c0 > r0)     s[nt][0] = -1e30f;
                if (c0 + 1 > r0) s[nt][1] = -1e30f;
                if (c0 > r1)     s[nt][2] = -1e30f;
                if (c0 + 1 > r1) s[nt][3] = -1e30f;
            }
        }

        float mx0 = -1e30f, mx1 = -1e30f;
        #pragma unroll
        for (int nt = 0; nt < 8; nt++) {
            mx0 = fmaxf(mx0, fmaxf(s[nt][0], s[nt][1]));
            mx1 = fmaxf(mx1, fmaxf(s[nt][2], s[nt][3]));
        }
        mx0 = fmaxf(mx0, __shfl_xor_sync(0xffffffffu, mx0, 1));
        mx0 = fmaxf(mx0, __shfl_xor_sync(0xffffffffu, mx0, 2));
        mx1 = fmaxf(mx1, __shfl_xor_sync(0xffffffffu, mx1, 1));
        mx1 = fmaxf(mx1, __shfl_xor_sync(0xffffffffu, mx1, 2));
        float mn0 = fmaxf(m0, mx0), mn1 = fmaxf(m1, mx1);
        float corr0 = __expf(m0 - mn0), corr1 = __expf(m1 - mn1);
        m0 = mn0; m1 = mn1;
        float sum0 = 0.f, sum1 = 0.f;
        #pragma unroll
        for (int nt = 0; nt < 8; nt++) {
            s[nt][0] = __expf(s[nt][0] - mn0);
            s[nt][1] = __expf(s[nt][1] - mn0);
            s[nt][2] = __expf(s[nt][2] - mn1);
            s[nt][3] = __expf(s[nt][3] - mn1);
            sum0 += s[nt][0] + s[nt][1];
            sum1 += s[nt][2] + s[nt][3];
        }
        l0 = l0 * corr0 + sum0;
        l1 = l1 * corr1 + sum1;
        #pragma unroll
        for (int nt = 0; nt < 8; nt++) {
            o[nt][0] *= corr0; o[nt][1] *= corr0;
            o[nt][2] *= corr1; o[nt][3] *= corr1;
        }

        uint32_t pt[8][4];
        #pragma unroll
        for (int nt = 0; nt < 8; nt++)
            #pragma unroll
            for (int c = 0; c < 4; c++) pt[nt][c] = f2tf(s[nt][c]);

        #pragma unroll
        for (int ks = 0; ks < 8; ks++) {
            uint32_t a[4];
            {
                uint32_t x0 = __shfl_sync(0xffffffffu, pt[ks][0], srcA);
                uint32_t x1 = __shfl_sync(0xffffffffu, pt[ks][1], srcA);
                a[0] = (t & 1) ? x1 : x0;
                uint32_t y0 = __shfl_sync(0xffffffffu, pt[ks][2], srcA);
                uint32_t y1 = __shfl_sync(0xffffffffu, pt[ks][3], srcA);
                a[1] = (t & 1) ? y1 : y0;
                uint32_t z0 = __shfl_sync(0xffffffffu, pt[ks][0], srcB);
                uint32_t z1 = __shfl_sync(0xffffffffu, pt[ks][1], srcB);
                a[2] = (t & 1) ? z1 : z0;
                uint32_t w0 = __shfl_sync(0xffffffffu, pt[ks][2], srcB);
                uint32_t w1 = __shfl_sync(0xffffffffu, pt[ks][3], srcB);
                a[3] = (t & 1) ? w1 : w0;
            }
            #pragma unroll
            for (int p = 0; p < 4; p++) {
                uint32_t bq[4];
                uint32_t baddr = vt_base
                               + (uint32_t)(((p * 16 + brow) * VT_S) * 4 + ks * 32 + bchunk);
                asm volatile(
                    "ldmatrix.sync.aligned.m8n8.x4.shared.b16 {%0,%1,%2,%3}, [%4];"
                    : "=r"(bq[0]), "=r"(bq[1]), "=r"(bq[2]), "=r"(bq[3]) : "r"(baddr));
                uint32_t b0[2] = {bq[0], bq[1]};
                uint32_t b1[2] = {bq[2], bq[3]};
                mma_tf32(o[2 * p], a, b0);
                mma_tf32(o[2 * p + 1], a, b1);
            }
        }
    }

    l0 += __shfl_xor_sync(0xffffffffu, l0, 1);
    l0 += __shfl_xor_sync(0xffffffffu, l0, 2);
    l1 += __shfl_xor_sync(0xffffffffu, l1, 1);
    l1 += __shfl_xor_sync(0xffffffffu, l1, 2);
    float inv0 = 1.f / l0, inv1 = 1.f / l1;

    int b_ = bh >> 4, h = bh & (NH - 1);
    int r0 = q0 + wp * 16 + g, r1 = r0 + 8;
    float* dst0 = g_ao + ((size_t)b_ * SEQ + r0) * DIM + h * HD;
    float* dst1 = g_ao + ((size_t)b_ * SEQ + r1) * DIM + h * HD;
    #pragma unroll
    for (int nt = 0; nt < 8; nt++) {
        int cc = nt * 8 + 2 * t;
        float2 o0, o1;
        o0.x = o[nt][0] * inv0; o0.y = o[nt][1] * inv0;
        o1.x = o[nt][2] * inv1; o1.y = o[nt][3] * inv1;
        *(float2*)(dst0 + cc) = o0;
        *(float2*)(dst1 + cc) = o1;
    }
}

// ---------------------------------------------------------------------------
extern "C" void kernel_launch(void* const* d_in, const int* in_sizes, int n_in,
                              void* d_out, int out_size) {
    const float* x     = (const float*)d_in[0];
    const float* W_qkv = (const float*)d_in[1];
    const float* b_qkv = (const float*)d_in[2];
    const float* W_out = (const float*)d_in[3];
    const float* b_out = (const float*)d_in[4];
    float* out = (float*)d_out;

    cudaFuncSetAttribute(attn_tc, cudaFuncAttributeMaxDynamicSharedMemorySize, ATTN_SMEM);

    gemm_qkv_tc<<<dim3(QKV_N / GBN, MROWS / GBM), 256>>>(x, W_qkv, b_qkv);
    attn_tc<<<dim3(SEQ / ATQ, BATCH * NH), 256, ATTN_SMEM>>>();
    gemm_out_tc<<<dim3(DIM / GBN, MROWS / GBM), 256>>>(W_out, b_out, out);
}

// round 6
// speedup vs baseline: 1.5011x; 1.5011x over previous
#include <cuda_runtime.h>
#include <cuda_bf16.h>
#include <cstdint>

// Problem constants
#define BATCH 2
#define SEQ   2048
#define DIM   1024
#define NH    16
#define HD    64
#define MROWS (BATCH*SEQ)          // 4096
#define QKV_N (3*DIM)              // 3072

// Scratch (device globals; no allocation allowed). All hold tf32-rounded fp32 bits
// except g_ao-consumers' outputs noted below.
__device__ float g_xt[MROWS*DIM];        // x, tf32-rounded
__device__ float g_wqkv[DIM*QKV_N];      // W_qkv, tf32-rounded
__device__ float g_wout[DIM*DIM];        // W_out, tf32-rounded
__device__ float g_q[BATCH*NH*SEQ*HD];   // [b][h][s][d], scaled+tf32
__device__ float g_k[BATCH*NH*SEQ*HD];   // [b][h][s][d], tf32
__device__ float g_vt[BATCH*NH*HD*SEQ];  // [b][h][d][s], tf32
__device__ float g_ao[BATCH*SEQ*DIM];    // attn out [b][s][h*64+d], tf32

__device__ __forceinline__ uint32_t f2tf(float x) {
    uint32_t y;
    asm("cvt.rna.tf32.f32 %0, %1;" : "=r"(y) : "f"(x));
    return y;
}
__device__ __forceinline__ float f2tff(float x) { return __uint_as_float(f2tf(x)); }

__device__ __forceinline__ void mma_tf32(float (&d)[4],
                                         const uint32_t (&a)[4],
                                         const uint32_t (&b)[2]) {
    asm volatile(
        "mma.sync.aligned.m16n8k8.row.col.f32.tf32.tf32.f32 "
        "{%0,%1,%2,%3}, {%4,%5,%6,%7}, {%8,%9}, {%0,%1,%2,%3};"
        : "+f"(d[0]), "+f"(d[1]), "+f"(d[2]), "+f"(d[3])
        : "r"(a[0]), "r"(a[1]), "r"(a[2]), "r"(a[3]), "r"(b[0]), "r"(b[1]));
}

__device__ __forceinline__ void cp_async16(uint32_t smem, const void* gptr) {
    asm volatile("cp.async.cg.shared.global [%0], [%1], 16;" :: "r"(smem), "l"(gptr));
}

// ---------------------------------------------------------------------------
// Pre-conversion kernel: fp32 -> tf32-rounded fp32 bits (vectorized).
// ---------------------------------------------------------------------------
__global__ void cvt_tf32_kernel(const float* __restrict__ src,
                                float* __restrict__ dst, int n4) {
    int i = blockIdx.x * blockDim.x + threadIdx.x;
    if (i < n4) {
        float4 v = ((const float4*)src)[i];
        float4 c;
        c.x = f2tff(v.x); c.y = f2tff(v.y); c.z = f2tff(v.z); c.w = f2tff(v.w);
        ((float4*)dst)[i] = c;
    }
}

// ---------------------------------------------------------------------------
// tf32 tensor-core GEMM: CTA 128x128x32, 8 warps (2m x 4n), warp 64x32.
// Inputs pre-converted. Staging via cp.async into double-buffered smem.
// Compute path identical to R4 (As row-major ldmatrix, Bs[k][n] scalar LDS).
// ---------------------------------------------------------------------------
#define GBM 128
#define GBN 128
#define GBK 32
#define AS_STRIDE 36
#define BS_STRIDE 136
#define GEMM_BUF (GBM*AS_STRIDE + GBK*BS_STRIDE)      // floats per stage buffer
#define GEMM_SMEM (2 * GEMM_BUF * 4)                  // bytes

__device__ __forceinline__ void gemm_tile_async(const float* __restrict__ A,
                                                const float* __restrict__ B,
                                                const int N,
                                                float (&acc)[4][4][4]) {
    extern __shared__ float smdyn[];

    const int K = DIM;
    const int tid = threadIdx.x;
    const int lane = tid & 31;
    const int w = tid >> 5;
    const int warpM = (w & 1) * 64;
    const int warpN = (w >> 1) * 32;
    const int g = lane >> 2;
    const int t = lane & 3;

    const float* Ag = A + (size_t)(blockIdx.y * GBM) * K;
    const float* Bg = B + blockIdx.x * GBN;

    const int sub = lane >> 3, r8 = lane & 7;
    const uint32_t lofA = (uint32_t)((((sub & 1) * 8 + r8) * AS_STRIDE) * 4 + (sub >> 1) * 16);
    const uint32_t sm_base = (uint32_t)__cvta_generic_to_shared(smdyn);

    const int a_row = tid >> 3;        // 0..31 (+ it*32)
    const int a_k4  = (tid & 7) * 4;
    const int b_k   = tid >> 5;        // 0..7 (+ it*8)
    const int b_n4  = (tid & 31) * 4;

    // stage tile kt into buffer buf (8 x cp.async.128 per thread)
    #define GEMM_STAGE(kt, buf)                                                      \
    {                                                                                \
        uint32_t as = sm_base + (uint32_t)((buf) * GEMM_BUF * 4);                    \
        uint32_t bs = as + (uint32_t)(GBM * AS_STRIDE * 4);                          \
        _Pragma("unroll")                                                            \
        for (int it = 0; it < 4; it++) {                                             \
            cp_async16(as + (uint32_t)(((a_row + it * 32) * AS_STRIDE + a_k4) * 4),  \
                       Ag + (size_t)(a_row + it * 32) * K + (kt) * GBK + a_k4);      \
            cp_async16(bs + (uint32_t)(((b_k + it * 8) * BS_STRIDE + b_n4) * 4),     \
                       Bg + (size_t)((kt) * GBK + b_k + it * 8) * N + b_n4);         \
        }                                                                            \
    }

    const int NKT = K / GBK;   // 32
    GEMM_STAGE(0, 0);
    asm volatile("cp.async.commit_group;");

    for (int kt = 0; kt < NKT; kt++) {
        if (kt + 1 < NKT) {
            GEMM_STAGE(kt + 1, (kt + 1) & 1);
            asm volatile("cp.async.commit_group;");
            asm volatile("cp.async.wait_group 1;");
        } else {
            asm volatile("cp.async.wait_group 0;");
        }
        __syncthreads();

        const float* Bsp = smdyn + (kt & 1) * GEMM_BUF + GBM * AS_STRIDE;
        const uint32_t as_b = sm_base + (uint32_t)((kt & 1) * GEMM_BUF * 4);

        #pragma unroll
        for (int ks = 0; ks < 4; ks++) {
            uint32_t af[4][4];
            #pragma unroll
            for (int mt = 0; mt < 4; mt++) {
                uint32_t addr = as_b
                              + (uint32_t)(((warpM + mt * 16) * AS_STRIDE) * 4 + ks * 32)
                              + lofA;
                asm volatile(
                    "ldmatrix.sync.aligned.m8n8.x4.shared.b16 {%0,%1,%2,%3}, [%4];"
                    : "=r"(af[mt][0]), "=r"(af[mt][1]), "=r"(af[mt][2]), "=r"(af[mt][3])
                    : "r"(addr));
            }
            uint32_t bf[4][2];
            #pragma unroll
            for (int nt = 0; nt < 4; nt++) {
                int n = warpN + nt * 8 + g;
                bf[nt][0] = __float_as_uint(Bsp[(ks * 8 + t) * BS_STRIDE + n]);
                bf[nt][1] = __float_as_uint(Bsp[(ks * 8 + t + 4) * BS_STRIDE + n]);
            }
            #pragma unroll
            for (int mt = 0; mt < 4; mt++)
                #pragma unroll
                for (int nt = 0; nt < 4; nt++)
                    mma_tf32(acc[mt][nt], af[mt], bf[nt]);
        }
        __syncthreads();
    }
    #undef GEMM_STAGE
}

__global__ __launch_bounds__(256) void gemm_qkv_tc(const float* __restrict__ bias) {
    float acc[4][4][4];
    #pragma unroll
    for (int i = 0; i < 4; i++)
        #pragma unroll
        for (int j = 0; j < 4; j++)
            #pragma unroll
            for (int k = 0; k < 4; k++) acc[i][j][k] = 0.f;

    gemm_tile_async(g_xt, g_wqkv, QKV_N, acc);

    const int tid = threadIdx.x;
    const int lane = tid & 31;
    const int w = tid >> 5;
    const int warpM = (w & 1) * 64;
    const int warpN = (w >> 1) * 32;
    const int g = lane >> 2, t = lane & 3;

    #pragma unroll
    for (int mt = 0; mt < 4; mt++) {
        #pragma unroll
        for (int nt = 0; nt < 4; nt++) {
            int col = blockIdx.x * GBN + warpN + nt * 8 + t * 2;
            float b0 = bias[col], b1 = bias[col + 1];
            int part = col >> 10;
            int h = (col >> 6) & (NH - 1);
            int d = col & (HD - 1);
            #pragma unroll
            for (int half = 0; half < 2; half++) {
                int r = blockIdx.y * GBM + warpM + mt * 16 + g + half * 8;
                int b_ = r >> 11, s = r & (SEQ - 1);
                float v0 = acc[mt][nt][half * 2 + 0] + b0;
                float v1 = acc[mt][nt][half * 2 + 1] + b1;
                if (part == 0) {
                    int idx = (((b_ * NH + h) * SEQ) + s) * HD + d;
                    g_q[idx]     = f2tff(v0 * 0.125f);
                    g_q[idx + 1] = f2tff(v1 * 0.125f);
                } else if (part == 1) {
                    int idx = (((b_ * NH + h) * SEQ) + s) * HD + d;
                    g_k[idx]     = f2tff(v0);
                    g_k[idx + 1] = f2tff(v1);
                } else {
                    size_t vb = ((size_t)(b_ * NH + h) * HD + d) * SEQ + s;
                    g_vt[vb]       = f2tff(v0);
                    g_vt[vb + SEQ] = f2tff(v1);
                }
            }
        }
    }
}

__global__ __launch_bounds__(256) void gemm_out_tc(const float* __restrict__ bias,
                                                   float* __restrict__ C) {
    float acc[4][4][4];
    #pragma unroll
    for (int i = 0; i < 4; i++)
        #pragma unroll
        for (int j = 0; j < 4; j++)
            #pragma unroll
            for (int k = 0; k < 4; k++) acc[i][j][k] = 0.f;

    gemm_tile_async(g_ao, g_wout, DIM, acc);

    const int tid = threadIdx.x;
    const int lane = tid & 31;
    const int w = tid >> 5;
    const int warpM = (w & 1) * 64;
    const int warpN = (w >> 1) * 32;
    const int g = lane >> 2, t = lane & 3;

    #pragma unroll
    for (int mt = 0; mt < 4; mt++) {
        #pragma unroll
        for (int nt = 0; nt < 4; nt++) {
            int col = blockIdx.x * GBN + warpN + nt * 8 + t * 2;
            float b0 = bias[col], b1 = bias[col + 1];
            #pragma unroll
            for (int half = 0; half < 2; half++) {
                int r = blockIdx.y * GBM + warpM + mt * 16 + g + half * 8;
                float2 o;
                o.x = acc[mt][nt][half * 2 + 0] + b0;
                o.y = acc[mt][nt][half * 2 + 1] + b1;
                *(float2*)(C + (size_t)r * DIM + col) = o;
            }
        }
    }
}

// ---------------------------------------------------------------------------
// Tensor-core causal flash attention (tf32 mma), all fragments via ldmatrix.
// Inputs pre-converted to tf32 by the QKV epilogue -> staging is pure copy.
// ---------------------------------------------------------------------------
#define ATQ 128
#define ATK 64
#define QS_S 68
#define KS_S 68
#define VT_S 68
#define ATTN_SMEM ((ATQ*QS_S + ATK*KS_S + HD*VT_S) * 4)

__global__ __launch_bounds__(256, 2) void attn_tc() {
    extern __shared__ float sm[];
    float* Qs = sm;                     // [128][68]  (q, d)
    float* Ks = Qs + ATQ * QS_S;        // [64][68]   (kv, d)
    float* Vt = Ks + ATK * KS_S;        // [64][68]   (d, kv)

    const int tid = threadIdx.x;
    const int lane = tid & 31;
    const int wp = tid >> 5;
    const int g = lane >> 2, t = lane & 3;

    const int qt = (gridDim.x - 1) - blockIdx.x;   // longest first
    const int bh = blockIdx.y;
    const int q0 = qt * ATQ;
    const float* Qp  = g_q  + (size_t)bh * SEQ * HD;
    const float* Kp  = g_k  + (size_t)bh * SEQ * HD;
    const float* Vtp = g_vt + (size_t)bh * HD * SEQ;

    const int sub = lane >> 3, r8 = lane & 7;
    const uint32_t lofQ = (uint32_t)((((sub & 1) * 8 + r8) * QS_S) * 4 + (sub >> 1) * 16);
    const int brow = (sub >> 1) * 8 + r8;
    const int bchunk = (sub & 1) * 16;
    const uint32_t qs_base = (uint32_t)__cvta_generic_to_shared(Qs);
    const uint32_t ks_base = (uint32_t)__cvta_generic_to_shared(Ks);
    const uint32_t vt_base = (uint32_t)__cvta_generic_to_shared(Vt);

    for (int i = tid; i < ATQ * (HD / 4); i += 256) {
        int r = i >> 4, c4 = (i & 15) * 4;
        *(float4*)&Qs[r * QS_S + c4] =
            *(const float4*)(Qp + (size_t)(q0 + r) * HD + c4);
    }

    float o[8][4];
    #pragma unroll
    for (int nt = 0; nt < 8; nt++)
        #pragma unroll
        for (int c = 0; c < 4; c++) o[nt][c] = 0.f;
    float m0 = -1e30f, m1 = -1e30f, l0 = 0.f, l1 = 0.f;

    const int srcA = (lane & ~3) | (t >> 1);
    const int srcB = srcA + 2;

    const int ntiles = 2 * qt + 2;
    for (int jt = 0; jt < ntiles; jt++) {
        if (jt) __syncthreads();
        const int kv0 = jt * ATK;
        for (int i = tid; i < ATK * (HD / 4); i += 256) {
            int r = i >> 4, c4 = (i & 15) * 4;
            *(float4*)&Ks[r * KS_S + c4] =
                *(const float4*)(Kp + (size_t)(kv0 + r) * HD + c4);
            *(float4*)&Vt[r * VT_S + c4] =
                *(const float4*)(Vtp + (size_t)r * SEQ + kv0 + c4);
        }
        __syncthreads();

        float s[8][4];
        #pragma unroll
        for (int nt = 0; nt < 8; nt++)
            #pragma unroll
            for (int c = 0; c < 4; c++) s[nt][c] = 0.f;

        #pragma unroll
        for (int ks = 0; ks < 8; ks++) {
            uint32_t a[4];
            uint32_t addr = qs_base
                          + (uint32_t)(((wp * 16) * QS_S) * 4 + ks * 32) + lofQ;
            asm volatile(
                "ldmatrix.sync.aligned.m8n8.x4.shared.b16 {%0,%1,%2,%3}, [%4];"
                : "=r"(a[0]), "=r"(a[1]), "=r"(a[2]), "=r"(a[3]) : "r"(addr));
            #pragma unroll
            for (int p = 0; p < 4; p++) {
                uint32_t bq[4];
                uint32_t baddr = ks_base
                               + (uint32_t)(((p * 16 + brow) * KS_S) * 4 + ks * 32 + bchunk);
                asm volatile(
                    "ldmatrix.sync.aligned.m8n8.x4.shared.b16 {%0,%1,%2,%3}, [%4];"
                    : "=r"(bq[0]), "=r"(bq[1]), "=r"(bq[2]), "=r"(bq[3]) : "r"(baddr));
                uint32_t b0[2] = {bq[0], bq[1]};
                uint32_t b1[2] = {bq[2], bq[3]};
                mma_tf32(s[2 * p], a, b0);
                mma_tf32(s[2 * p + 1], a, b1);
            }
        }

        if (jt >= 2 * qt) {
            int r0 = q0 + wp * 16 + g, r1 = r0 + 8;
            #pragma unroll
            for (int nt = 0; nt < 8; nt++) {
                int c0 = kv0 + nt * 8 + 2 * t;
                if (c0 > r0)     s[nt][0] = -1e30f;
                if (c0 + 1 > r0) s[nt][1] = -1e30f;
                if (c0 > r1)     s[nt][2] = -1e30f;
                if (c0 + 1 > r1) s[nt][3] = -1e30f;
            }
        }

        float mx0 = -1e30f, mx1 = -1e30f;
        #pragma unroll
        for (int nt = 0; nt < 8; nt++) {
            mx0 = fmaxf(mx0, fmaxf(s[nt][0], s[nt][1]));
            mx1 = fmaxf(mx1, fmaxf(s[nt][2], s[nt][3]));
        }
        mx0 = fmaxf(mx0, __shfl_xor_sync(0xffffffffu, mx0, 1));
        mx0 = fmaxf(mx0, __shfl_xor_sync(0xffffffffu, mx0, 2));
        mx1 = fmaxf(mx1, __shfl_xor_sync(0xffffffffu, mx1, 1));
        mx1 = fmaxf(mx1, __shfl_xor_sync(0xffffffffu, mx1, 2));
        float mn0 = fmaxf(m0, mx0), mn1 = fmaxf(m1, mx1);
        float corr0 = __expf(m0 - mn0), corr1 = __expf(m1 - mn1);
        m0 = mn0; m1 = mn1;
        float sum0 = 0.f, sum1 = 0.f;
        #pragma unroll
        for (int nt = 0; nt < 8; nt++) {
            s[nt][0] = __expf(s[nt][0] - mn0);
            s[nt][1] = __expf(s[nt][1] - mn0);
            s[nt][2] = __expf(s[nt][2] - mn1);
            s[nt][3] = __expf(s[nt][3] - mn1);
            sum0 += s[nt][0] + s[nt][1];
            sum1 += s[nt][2] + s[nt][3];
        }
        l0 = l0 * corr0 + sum0;
        l1 = l1 * corr1 + sum1;
        #pragma unroll
        for (int nt = 0; nt < 8; nt++) {
            o[nt][0] *= corr0; o[nt][1] *= corr0;
            o[nt][2] *= corr1; o[nt][3] *= corr1;
        }

        uint32_t pt[8][4];
        #pragma unroll
        for (int nt = 0; nt < 8; nt++)
            #pragma unroll
            for (int c = 0; c < 4; c++) pt[nt][c] = f2tf(s[nt][c]);

        #pragma unroll
        for (int ks = 0; ks < 8; ks++) {
            uint32_t a[4];
            {
                uint32_t x0 = __shfl_sync(0xffffffffu, pt[ks][0], srcA);
                uint32_t x1 = __shfl_sync(0xffffffffu, pt[ks][1], srcA);
                a[0] = (t & 1) ? x1 : x0;
                uint32_t y0 = __shfl_sync(0xffffffffu, pt[ks][2], srcA);
                uint32_t y1 = __shfl_sync(0xffffffffu, pt[ks][3], srcA);
                a[1] = (t & 1) ? y1 : y0;
                uint32_t z0 = __shfl_sync(0xffffffffu, pt[ks][0], srcB);
                uint32_t z1 = __shfl_sync(0xffffffffu, pt[ks][1], srcB);
                a[2] = (t & 1) ? z1 : z0;
                uint32_t w0 = __shfl_sync(0xffffffffu, pt[ks][2], srcB);
                uint32_t w1 = __shfl_sync(0xffffffffu, pt[ks][3], srcB);
                a[3] = (t & 1) ? w1 : w0;
            }
            #pragma unroll
            for (int p = 0; p < 4; p++) {
                uint32_t bq[4];
                uint32_t baddr = vt_base
                               + (uint32_t)(((p * 16 + brow) * VT_S) * 4 + ks * 32 + bchunk);
                asm volatile(
                    "ldmatrix.sync.aligned.m8n8.x4.shared.b16 {%0,%1,%2,%3}, [%4];"
                    : "=r"(bq[0]), "=r"(bq[1]), "=r"(bq[2]), "=r"(bq[3]) : "r"(baddr));
                uint32_t b0[2] = {bq[0], bq[1]};
                uint32_t b1[2] = {bq[2], bq[3]};
                mma_tf32(o[2 * p], a, b0);
                mma_tf32(o[2 * p + 1], a, b1);
            }
        }
    }

    l0 += __shfl_xor_sync(0xffffffffu, l0, 1);
    l0 += __shfl_xor_sync(0xffffffffu, l0, 2);
    l1 += __shfl_xor_sync(0xffffffffu, l1, 1);
    l1 += __shfl_xor_sync(0xffffffffu, l1, 2);
    float inv0 = 1.f / l0, inv1 = 1.f / l1;

    int b_ = bh >> 4, h = bh & (NH - 1);
    int r0 = q0 + wp * 16 + g, r1 = r0 + 8;
    float* dst0 = g_ao + ((size_t)b_ * SEQ + r0) * DIM + h * HD;
    float* dst1 = g_ao + ((size_t)b_ * SEQ + r1) * DIM + h * HD;
    #pragma unroll
    for (int nt = 0; nt < 8; nt++) {
        int cc = nt * 8 + 2 * t;
        float2 o0, o1;
        o0.x = f2tff(o[nt][0] * inv0); o0.y = f2tff(o[nt][1] * inv0);
        o1.x = f2tff(o[nt][2] * inv1); o1.y = f2tff(o[nt][3] * inv1);
        *(float2*)(dst0 + cc) = o0;
        *(float2*)(dst1 + cc) = o1;
    }
}

// ---------------------------------------------------------------------------
extern "C" void kernel_launch(void* const* d_in, const int* in_sizes, int n_in,
                              void* d_out, int out_size) {
    const float* x     = (const float*)d_in[0];
    const float* W_qkv = (const float*)d_in[1];
    const float* b_qkv = (const float*)d_in[2];
    const float* W_out = (const float*)d_in[3];
    const float* b_out = (const float*)d_in[4];
    float* out = (float*)d_out;

    static float* p_xt = nullptr;
    static float* p_wqkv = nullptr;
    static float* p_wout = nullptr;
    if (!p_xt) {
        cudaGetSymbolAddress((void**)&p_xt, g_xt);
        cudaGetSymbolAddress((void**)&p_wqkv, g_wqkv);
        cudaGetSymbolAddress((void**)&p_wout, g_wout);
        cudaFuncSetAttribute(attn_tc, cudaFuncAttributeMaxDynamicSharedMemorySize, ATTN_SMEM);
        cudaFuncSetAttribute(gemm_qkv_tc, cudaFuncAttributeMaxDynamicSharedMemorySize, GEMM_SMEM);
        cudaFuncSetAttribute(gemm_out_tc, cudaFuncAttributeMaxDynamicSharedMemorySize, GEMM_SMEM);
    }

    // Pre-convert inputs to tf32 (identical values to converting at stage time)
    cvt_tf32_kernel<<<(MROWS*DIM/4 + 255)/256, 256>>>(x, p_xt, MROWS*DIM/4);
    cvt_tf32_kernel<<<(DIM*QKV_N/4 + 255)/256, 256>>>(W_qkv, p_wqkv, DIM*QKV_N/4);
    cvt_tf32_kernel<<<(DIM*DIM/4 + 255)/256, 256>>>(W_out, p_wout, DIM*DIM/4);

    gemm_qkv_tc<<<dim3(QKV_N / GBN, MROWS / GBM), 256, GEMM_SMEM>>>(b_qkv);
    attn_tc<<<dim3(SEQ / ATQ, BATCH * NH), 256, ATTN_SMEM>>>();
    gemm_out_tc<<<dim3(DIM / GBN, MROWS / GBM), 256, GEMM_SMEM>>>(b_out, out);
}

// round 7
// speedup vs baseline: 1.5705x; 1.0462x over previous
#include <cuda_runtime.h>
#include <cuda_bf16.h>
#include <cstdint>

// Problem constants
#define BATCH 2
#define SEQ   2048
#define DIM   1024
#define NH    16
#define HD    64
#define MROWS (BATCH*SEQ)          // 4096
#define QKV_N (3*DIM)              // 3072

// Scratch (device globals; no allocation allowed).
__device__ float g_xt[MROWS*DIM];        // x, tf32-rounded
__device__ float g_wqkv[DIM*QKV_N];      // W_qkv, tf32-rounded
__device__ float g_wout[DIM*DIM];       // W_out, tf32-rounded
__device__ float g_q[BATCH*NH*SEQ*HD];   // [b][h][s][d], scaled+tf32
__device__ float g_k[BATCH*NH*SEQ*HD];   // [b][h][s][d], tf32
__device__ float g_vt[BATCH*NH*HD*SEQ];  // [b][h][d][s], tf32
__device__ float g_ao[BATCH*SEQ*DIM];    // attn out [b][s][h*64+d], tf32

__device__ __forceinline__ uint32_t f2tf(float x) {
    uint32_t y;
    asm("cvt.rna.tf32.f32 %0, %1;" : "=r"(y) : "f"(x));
    return y;
}
__device__ __forceinline__ float f2tff(float x) { return __uint_as_float(f2tf(x)); }

__device__ __forceinline__ void mma_tf32(float (&d)[4],
                                         const uint32_t (&a)[4],
                                         const uint32_t (&b)[2]) {
    asm volatile(
        "mma.sync.aligned.m16n8k8.row.col.f32.tf32.tf32.f32 "
        "{%0,%1,%2,%3}, {%4,%5,%6,%7}, {%8,%9}, {%0,%1,%2,%3};"
        : "+f"(d[0]), "+f"(d[1]), "+f"(d[2]), "+f"(d[3])
        : "r"(a[0]), "r"(a[1]), "r"(a[2]), "r"(a[3]), "r"(b[0]), "r"(b[1]));
}

__device__ __forceinline__ void cp_async16(uint32_t smem, const void* gptr) {
    asm volatile("cp.async.cg.shared.global [%0], [%1], 16;" :: "r"(smem), "l"(gptr));
}

// ---------------------------------------------------------------------------
// Pre-conversion kernel: fp32 -> tf32-rounded fp32 bits (vectorized).
// ---------------------------------------------------------------------------
__global__ void cvt_tf32_kernel(const float* __restrict__ src,
                                float* __restrict__ dst, int n4) {
    int i = blockIdx.x * blockDim.x + threadIdx.x;
    if (i < n4) {
        float4 v = ((const float4*)src)[i];
        float4 c;
        c.x = f2tff(v.x); c.y = f2tff(v.y); c.z = f2tff(v.z); c.w = f2tff(v.w);
        ((float4*)dst)[i] = c;
    }
}

// ---------------------------------------------------------------------------
// tf32 tensor-core GEMM: CTA 128x128x32, 8 warps (2m x 4n), warp 64x32.
// cp.async double buffer, ONE __syncthreads per k-tile:
//   wait(kt) -> sync -> issue stage(kt+1) -> compute(kt)
// ---------------------------------------------------------------------------
#define GBM 128
#define GBN 128
#define GBK 32
#define AS_STRIDE 36
#define BS_STRIDE 136
#define GEMM_BUF (GBM*AS_STRIDE + GBK*BS_STRIDE)      // floats per stage buffer
#define GEMM_SMEM (2 * GEMM_BUF * 4)                  // bytes

__device__ __forceinline__ void gemm_tile_async(const float* __restrict__ A,
                                                const float* __restrict__ B,
                                                const int N,
                                                float (&acc)[4][4][4]) {
    extern __shared__ float smdyn[];

    const int K = DIM;
    const int tid = threadIdx.x;
    const int lane = tid & 31;
    const int w = tid >> 5;
    const int warpM = (w & 1) * 64;
    const int warpN = (w >> 1) * 32;
    const int g = lane >> 2;
    const int t = lane & 3;

    const float* Ag = A + (size_t)(blockIdx.y * GBM) * K;
    const float* Bg = B + blockIdx.x * GBN;

    const int sub = lane >> 3, r8 = lane & 7;
    const uint32_t lofA = (uint32_t)((((sub & 1) * 8 + r8) * AS_STRIDE) * 4 + (sub >> 1) * 16);
    const uint32_t sm_base = (uint32_t)__cvta_generic_to_shared(smdyn);

    const int a_row = tid >> 3;        // 0..31 (+ it*32)
    const int a_k4  = (tid & 7) * 4;
    const int b_k   = tid >> 5;        // 0..7 (+ it*8)
    const int b_n4  = (tid & 31) * 4;

    #define GEMM_STAGE(kt, buf)                                                      \
    {                                                                                \
        uint32_t as = sm_base + (uint32_t)((buf) * GEMM_BUF * 4);                    \
        uint32_t bs = as + (uint32_t)(GBM * AS_STRIDE * 4);                          \
        _Pragma("unroll")                                                            \
        for (int it = 0; it < 4; it++) {                                             \
            cp_async16(as + (uint32_t)(((a_row + it * 32) * AS_STRIDE + a_k4) * 4),  \
                       Ag + (size_t)(a_row + it * 32) * K + (kt) * GBK + a_k4);      \
            cp_async16(bs + (uint32_t)(((b_k + it * 8) * BS_STRIDE + b_n4) * 4),     \
                       Bg + (size_t)((kt) * GBK + b_k + it * 8) * N + b_n4);         \
        }                                                                            \
    }

    const int NKT = K / GBK;   // 32
    GEMM_STAGE(0, 0);
    asm volatile("cp.async.commit_group;");

    for (int kt = 0; kt < NKT; kt++) {
        asm volatile("cp.async.wait_group 0;");
        __syncthreads();
        if (kt + 1 < NKT) {
            GEMM_STAGE(kt + 1, (kt + 1) & 1);
            asm volatile("cp.async.commit_group;");
        }

        const float* Bsp = smdyn + (kt & 1) * GEMM_BUF + GBM * AS_STRIDE;
        const uint32_t as_b = sm_base + (uint32_t)((kt & 1) * GEMM_BUF * 4);

        #pragma unroll
        for (int ks = 0; ks < 4; ks++) {
            uint32_t af[4][4];
            #pragma unroll
            for (int mt = 0; mt < 4; mt++) {
                uint32_t addr = as_b
                              + (uint32_t)(((warpM + mt * 16) * AS_STRIDE) * 4 + ks * 32)
                              + lofA;
                asm volatile(
                    "ldmatrix.sync.aligned.m8n8.x4.shared.b16 {%0,%1,%2,%3}, [%4];"
                    : "=r"(af[mt][0]), "=r"(af[mt][1]), "=r"(af[mt][2]), "=r"(af[mt][3])
                    : "r"(addr));
            }
            uint32_t bf[4][2];
            #pragma unroll
            for (int nt = 0; nt < 4; nt++) {
                int n = warpN + nt * 8 + g;
                bf[nt][0] = __float_as_uint(Bsp[(ks * 8 + t) * BS_STRIDE + n]);
                bf[nt][1] = __float_as_uint(Bsp[(ks * 8 + t + 4) * BS_STRIDE + n]);
            }
            #pragma unroll
            for (int mt = 0; mt < 4; mt++)
                #pragma unroll
                for (int nt = 0; nt < 4; nt++)
                    mma_tf32(acc[mt][nt], af[mt], bf[nt]);
        }
    }
    #undef GEMM_STAGE
}

__global__ __launch_bounds__(256) void gemm_qkv_tc(const float* __restrict__ bias) {
    float acc[4][4][4];
    #pragma unroll
    for (int i = 0; i < 4; i++)
        #pragma unroll
        for (int j = 0; j < 4; j++)
            #pragma unroll
            for (int k = 0; k < 4; k++) acc[i][j][k] = 0.f;

    gemm_tile_async(g_xt, g_wqkv, QKV_N, acc);

    const int tid = threadIdx.x;
    const int lane = tid & 31;
    const int w = tid >> 5;
    const int warpM = (w & 1) * 64;
    const int warpN = (w >> 1) * 32;
    const int g = lane >> 2, t = lane & 3;

    #pragma unroll
    for (int mt = 0; mt < 4; mt++) {
        #pragma unroll
        for (int nt = 0; nt < 4; nt++) {
            int col = blockIdx.x * GBN + warpN + nt * 8 + t * 2;
            float b0 = bias[col], b1 = bias[col + 1];
            int part = col >> 10;
            int h = (col >> 6) & (NH - 1);
            int d = col & (HD - 1);
            #pragma unroll
            for (int half = 0; half < 2; half++) {
                int r = blockIdx.y * GBM + warpM + mt * 16 + g + half * 8;
                int b_ = r >> 11, s = r & (SEQ - 1);
                float v0 = acc[mt][nt][half * 2 + 0] + b0;
                float v1 = acc[mt][nt][half * 2 + 1] + b1;
                if (part == 0) {
                    int idx = (((b_ * NH + h) * SEQ) + s) * HD + d;
                    g_q[idx]     = f2tff(v0 * 0.125f);
                    g_q[idx + 1] = f2tff(v1 * 0.125f);
                } else if (part == 1) {
                    int idx = (((b_ * NH + h) * SEQ) + s) * HD + d;
                    g_k[idx]     = f2tff(v0);
                    g_k[idx + 1] = f2tff(v1);
                } else {
                    size_t vb = ((size_t)(b_ * NH + h) * HD + d) * SEQ + s;
                    g_vt[vb]       = f2tff(v0);
                    g_vt[vb + SEQ] = f2tff(v1);
                }
            }
        }
    }
}

__global__ __launch_bounds__(256) void gemm_out_tc(const float* __restrict__ bias,
                                                   float* __restrict__ C) {
    float acc[4][4][4];
    #pragma unroll
    for (int i = 0; i < 4; i++)
        #pragma unroll
        for (int j = 0; j < 4; j++)
            #pragma unroll
            for (int k = 0; k < 4; k++) acc[i][j][k] = 0.f;

    gemm_tile_async(g_ao, g_wout, DIM, acc);

    const int tid = threadIdx.x;
    const int lane = tid & 31;
    const int w = tid >> 5;
    const int warpM = (w & 1) * 64;
    const int warpN = (w >> 1) * 32;
    const int g = lane >> 2, t = lane & 3;

    #pragma unroll
    for (int mt = 0; mt < 4; mt++) {
        #pragma unroll
        for (int nt = 0; nt < 4; nt++) {
            int col = blockIdx.x * GBN + warpN + nt * 8 + t * 2;
            float b0 = bias[col], b1 = bias[col + 1];
            #pragma unroll
            for (int half = 0; half < 2; half++) {
                int r = blockIdx.y * GBM + warpM + mt * 16 + g + half * 8;
                float2 o;
                o.x = acc[mt][nt][half * 2 + 0] + b0;
                o.y = acc[mt][nt][half * 2 + 1] + b1;
                *(float2*)(C + (size_t)r * DIM + col) = o;
            }
        }
    }
}

// ---------------------------------------------------------------------------
// Tensor-core causal flash attention (tf32 mma), all fragments via ldmatrix.
// K/V staged via cp.async double buffer, ONE __syncthreads per kv-tile.
// ---------------------------------------------------------------------------
#define ATQ 128
#define ATK 64
#define QS_S 68
#define KS_S 68
#define VT_S 68
#define ATTN_BUF (ATK*KS_S + HD*VT_S)          // floats per K/V stage
#define ATTN_SMEM ((ATQ*QS_S + 2*ATTN_BUF) * 4)

__global__ __launch_bounds__(256, 2) void attn_tc() {
    extern __shared__ float sm[];
    float* Qs = sm;                     // [128][68]  (q, d)
    // K/V stage buffers follow: buf b at Qs + ATQ*QS_S + b*ATTN_BUF

    const int tid = threadIdx.x;
    const int lane = tid & 31;
    const int wp = tid >> 5;
    const int g = lane >> 2, t = lane & 3;

    const int qt = (gridDim.x - 1) - blockIdx.x;   // longest first
    const int bh = blockIdx.y;
    const int q0 = qt * ATQ;
    const float* Qp  = g_q  + (size_t)bh * SEQ * HD;
    const float* Kp  = g_k  + (size_t)bh * SEQ * HD;
    const float* Vtp = g_vt + (size_t)bh * HD * SEQ;

    const int sub = lane >> 3, r8 = lane & 7;
    const uint32_t lofQ = (uint32_t)((((sub & 1) * 8 + r8) * QS_S) * 4 + (sub >> 1) * 16);
    const int brow = (sub >> 1) * 8 + r8;
    const int bchunk = (sub & 1) * 16;
    const uint32_t qs_base = (uint32_t)__cvta_generic_to_shared(Qs);
    const uint32_t kv_base0 = qs_base + (uint32_t)(ATQ * QS_S * 4);

    // staging coords: 4 float4 per thread for K, 4 for Vt
    const int st_r  = tid >> 4;          // 0..15 (+ it*16)
    const int st_c4 = (tid & 15) * 4;

    #define ATTN_STAGE(jt, buf)                                                       \
    {                                                                                 \
        uint32_t ksb = kv_base0 + (uint32_t)((buf) * ATTN_BUF * 4);                   \
        uint32_t vtb = ksb + (uint32_t)(ATK * KS_S * 4);                              \
        int kv0_ = (jt) * ATK;                                                        \
        _Pragma("unroll")                                                             \
        for (int it = 0; it < 4; it++) {                                              \
            int r = st_r + it * 16;                                                   \
            cp_async16(ksb + (uint32_t)((r * KS_S + st_c4) * 4),                      \
                       Kp + (size_t)(kv0_ + r) * HD + st_c4);                         \
            cp_async16(vtb + (uint32_t)((r * VT_S + st_c4) * 4),                      \
                       Vtp + (size_t)r * SEQ + kv0_ + st_c4);                         \
        }                                                                             \
    }

    // Load Q tile (plain copies; values already tf32)
    for (int i = tid; i < ATQ * (HD / 4); i += 256) {
        int r = i >> 4, c4 = (i & 15) * 4;
        *(float4*)&Qs[r * QS_S + c4] =
            *(const float4*)(Qp + (size_t)(q0 + r) * HD + c4);
    }

    float o[8][4];
    #pragma unroll
    for (int nt = 0; nt < 8; nt++)
        #pragma unroll
        for (int c = 0; c < 4; c++) o[nt][c] = 0.f;
    float m0 = -1e30f, m1 = -1e30f, l0 = 0.f, l1 = 0.f;

    const int srcA = (lane & ~3) | (t >> 1);
    const int srcB = srcA + 2;

    const int ntiles = 2 * qt + 2;
    ATTN_STAGE(0, 0);
    asm volatile("cp.async.commit_group;");

    for (int jt = 0; jt < ntiles; jt++) {
        asm volatile("cp.async.wait_group 0;");
        __syncthreads();
        if (jt + 1 < ntiles) {
            ATTN_STAGE(jt + 1, (jt + 1) & 1);
            asm volatile("cp.async.commit_group;");
        }
        const int kv0 = jt * ATK;
        const uint32_t ks_base = kv_base0 + (uint32_t)((jt & 1) * ATTN_BUF * 4);
        const uint32_t vt_base = ks_base + (uint32_t)(ATK * KS_S * 4);

        float s[8][4];
        #pragma unroll
        for (int nt = 0; nt < 8; nt++)
            #pragma unroll
            for (int c = 0; c < 4; c++) s[nt][c] = 0.f;

        #pragma unroll
        for (int ks = 0; ks < 8; ks++) {
            uint32_t a[4];
            uint32_t addr = qs_base
                          + (uint32_t)(((wp * 16) * QS_S) * 4 + ks * 32) + lofQ;
            asm volatile(
                "ldmatrix.sync.aligned.m8n8.x4.shared.b16 {%0,%1,%2,%3}, [%4];"
                : "=r"(a[0]), "=r"(a[1]), "=r"(a[2]), "=r"(a[3]) : "r"(addr));
            #pragma unroll
            for (int p = 0; p < 4; p++) {
                uint32_t bq[4];
                uint32_t baddr = ks_base
                               + (uint32_t)(((p * 16 + brow) * KS_S) * 4 + ks * 32 + bchunk);
                asm volatile(
                    "ldmatrix.sync.aligned.m8n8.x4.shared.b16 {%0,%1,%2,%3}, [%4];"
                    : "=r"(bq[0]), "=r"(bq[1]), "=r"(bq[2]), "=r"(bq[3]) : "r"(baddr));
                uint32_t b0[2] = {bq[0], bq[1]};
                uint32_t b1[2] = {bq[2], bq[3]};
                mma_tf32(s[2 * p], a, b0);
                mma_tf32(s[2 * p + 1], a, b1);
            }
        }

        if (jt >= 2 * qt) {
            int r0 = q0 + wp * 16 + g, r1 = r0 + 8;
            #pragma unroll
            for (int nt = 0; nt < 8; nt++) {
                int c0 = kv0 + nt * 8 + 2 * t;
                if (c0 > r0)     s[nt][0] = -1e30f;
                if (c0 + 1 > r0) s[nt][1] = -1e30f;
                if (c0 > r1)     s[nt][2] = -1e30f;
                if (c0 + 1 > r1) s[nt][3] = -1e30f;
            }
        }

        float mx0 = -1e30f, mx1 = -1e30f;
        #pragma unroll
        for (int nt = 0; nt < 8; nt++) {
            mx0 = fmaxf(mx0, fmaxf(s[nt][0], s[nt][1]));
            mx1 = fmaxf(mx1, fmaxf(s[nt][2], s[nt][3]));
        }
        mx0 = fmaxf(mx0, __shfl_xor_sync(0xffffffffu, mx0, 1));
        mx0 = fmaxf(mx0, __shfl_xor_sync(0xffffffffu, mx0, 2));
        mx1 = fmaxf(mx1, __shfl_xor_sync(0xffffffffu, mx1, 1));
        mx1 = fmaxf(mx1, __shfl_xor_sync(0xffffffffu, mx1, 2));
        float mn0 = fmaxf(m0, mx0), mn1 = fmaxf(m1, mx1);
        float corr0 = __expf(m0 - mn0), corr1 = __expf(m1 - mn1);
        m0 = mn0; m1 = mn1;
        float sum0 = 0.f, sum1 = 0.f;
        #pragma unroll
        for (int nt = 0; nt < 8; nt++) {
            s[nt][0] = __expf(s[nt][0] - mn0);
            s[nt][1] = __expf(s[nt][1] - mn0);
            s[nt][2] = __expf(s[nt][2] - mn1);
            s[nt][3] = __expf(s[nt][3] - mn1);
            sum0 += s[nt][0] + s[nt][1];
            sum1 += s[nt][2] + s[nt][3];
        }
        l0 = l0 * corr0 + sum0;
        l1 = l1 * corr1 + sum1;
        #pragma unroll
        for (int nt = 0; nt < 8; nt++) {
            o[nt][0] *= corr0; o[nt][1] *= corr0;
            o[nt][2] *= corr1; o[nt][3] *= corr1;
        }

        uint32_t pt[8][4];
        #pragma unroll
        for (int nt = 0; nt < 8; nt++)
            #pragma unroll
            for (int c = 0; c < 4; c++) pt[nt][c] = f2tf(s[nt][c]);

        #pragma unroll
        for (int ks = 0; ks < 8; ks++) {
            uint32_t a[4];
            {
                uint32_t x0 = __shfl_sync(0xffffffffu, pt[ks][0], srcA);
                uint32_t x1 = __shfl_sync(0xffffffffu, pt[ks][1], srcA);
                a[0] = (t & 1) ? x1 : x0;
                uint32_t y0 = __shfl_sync(0xffffffffu, pt[ks][2], srcA);
                uint32_t y1 = __shfl_sync(0xffffffffu, pt[ks][3], srcA);
                a[1] = (t & 1) ? y1 : y0;
                uint32_t z0 = __shfl_sync(0xffffffffu, pt[ks][0], srcB);
                uint32_t z1 = __shfl_sync(0xffffffffu, pt[ks][1], srcB);
                a[2] = (t & 1) ? z1 : z0;
                uint32_t w0 = __shfl_sync(0xffffffffu, pt[ks][2], srcB);
                uint32_t w1 = __shfl_sync(0xffffffffu, pt[ks][3], srcB);
                a[3] = (t & 1) ? w1 : w0;
            }
            #pragma unroll
            for (int p = 0; p < 4; p++) {
                uint32_t bq[4];
                uint32_t baddr = vt_base
                               + (uint32_t)(((p * 16 + brow) * VT_S) * 4 + ks * 32 + bchunk);
                asm volatile(
                    "ldmatrix.sync.aligned.m8n8.x4.shared.b16 {%0,%1,%2,%3}, [%4];"
                    : "=r"(bq[0]), "=r"(bq[1]), "=r"(bq[2]), "=r"(bq[3]) : "r"(baddr));
                uint32_t b0[2] = {bq[0], bq[1]};
                uint32_t b1[2] = {bq[2], bq[3]};
                mma_tf32(o[2 * p], a, b0);
                mma_tf32(o[2 * p + 1], a, b1);
            }
        }
    }
    #undef ATTN_STAGE

    l0 += __shfl_xor_sync(0xffffffffu, l0, 1);
    l0 += __shfl_xor_sync(0xffffffffu, l0, 2);
    l1 += __shfl_xor_sync(0xffffffffu, l1, 1);
    l1 += __shfl_xor_sync(0xffffffffu, l1, 2);
    float inv0 = 1.f / l0, inv1 = 1.f / l1;

    int b_ = bh >> 4, h = bh & (NH - 1);
    int r0 = q0 + wp * 16 + g, r1 = r0 + 8;
    float* dst0 = g_ao + ((size_t)b_ * SEQ + r0) * DIM + h * HD;
    float* dst1 = g_ao + ((size_t)b_ * SEQ + r1) * DIM + h * HD;
    #pragma unroll
    for (int nt = 0; nt < 8; nt++) {
        int cc = nt * 8 + 2 * t;
        float2 o0, o1;
        o0.x = f2tff(o[nt][0] * inv0); o0.y = f2tff(o[nt][1] * inv0);
        o1.x = f2tff(o[nt][2] * inv1); o1.y = f2tff(o[nt][3] * inv1);
        *(float2*)(dst0 + cc) = o0;
        *(float2*)(dst1 + cc) = o1;
    }
}

// ---------------------------------------------------------------------------
extern "C" void kernel_launch(void* const* d_in, const int* in_sizes, int n_in,
                              void* d_out, int out_size) {
    const float* x     = (const float*)d_in[0];
    const float* W_qkv = (const float*)d_in[1];
    const float* b_qkv = (const float*)d_in[2];
    const float* W_out = (const float*)d_in[3];
    const float* b_out = (const float*)d_in[4];
    float* out = (float*)d_out;

    static float* p_xt = nullptr;
    static float* p_wqkv = nullptr;
    static float* p_wout = nullptr;
    if (!p_xt) {
        cudaGetSymbolAddress((void**)&p_xt, g_xt);
        cudaGetSymbolAddress((void**)&p_wqkv, g_wqkv);
        cudaGetSymbolAddress((void**)&p_wout, g_wout);
        cudaFuncSetAttribute(attn_tc, cudaFuncAttributeMaxDynamicSharedMemorySize, ATTN_SMEM);
        cudaFuncSetAttribute(gemm_qkv_tc, cudaFuncAttributeMaxDynamicSharedMemorySize, GEMM_SMEM);
        cudaFuncSetAttribute(gemm_out_tc, cudaFuncAttributeMaxDynamicSharedMemorySize, GEMM_SMEM);
    }

    cvt_tf32_kernel<<<(MROWS*DIM/4 + 255)/256, 256>>>(x, p_xt, MROWS*DIM/4);
    cvt_tf32_kernel<<<(DIM*QKV_N/4 + 255)/256, 256>>>(W_qkv, p_wqkv, DIM*QKV_N/4);
    cvt_tf32_kernel<<<(DIM*DIM/4 + 255)/256, 256>>>(W_out, p_wout, DIM*DIM/4);

    gemm_qkv_tc<<<dim3(QKV_N / GBN, MROWS / GBM), 256, GEMM_SMEM>>>(b_qkv);
    attn_tc<<<dim3(SEQ / ATQ, BATCH * NH), 256, ATTN_SMEM>>>();
    gemm_out_tc<<<dim3(DIM / GBN, MROWS / GBM), 256, GEMM_SMEM>>>(b_out, out);
}

// round 8
// speedup vs baseline: 1.5720x; 1.0009x over previous
#include <cuda_runtime.h>
#include <cuda_bf16.h>
#include <cstdint>

// Problem constants
#define BATCH 2
#define SEQ   2048
#define DIM   1024
#define NH    16
#define HD    64
#define MROWS (BATCH*SEQ)          // 4096
#define QKV_N (3*DIM)              // 3072

// Scratch (device globals; no allocation allowed).
__device__ float g_xt[MROWS*DIM];        // x, tf32-rounded
__device__ float g_wqkvt[QKV_N*DIM];     // W_qkv^T [n][k], tf32-rounded
__device__ float g_woutt[DIM*DIM];       // W_out^T [n][k], tf32-rounded
__device__ float g_q[BATCH*NH*SEQ*HD];   // [b][h][s][d], scaled+tf32
__device__ float g_k[BATCH*NH*SEQ*HD];   // [b][h][s][d], tf32
__device__ float g_vt[BATCH*NH*HD*SEQ];  // [b][h][d][s], tf32
__device__ float g_ao[BATCH*SEQ*DIM];    // attn out [b][s][h*64+d], tf32

__device__ __forceinline__ uint32_t f2tf(float x) {
    uint32_t y;
    asm("cvt.rna.tf32.f32 %0, %1;" : "=r"(y) : "f"(x));
    return y;
}
__device__ __forceinline__ float f2tff(float x) { return __uint_as_float(f2tf(x)); }

__device__ __forceinline__ void mma_tf32(float (&d)[4],
                                         const uint32_t (&a)[4],
                                         const uint32_t (&b)[2]) {
    asm volatile(
        "mma.sync.aligned.m16n8k8.row.col.f32.tf32.tf32.f32 "
        "{%0,%1,%2,%3}, {%4,%5,%6,%7}, {%8,%9}, {%0,%1,%2,%3};"
        : "+f"(d[0]), "+f"(d[1]), "+f"(d[2]), "+f"(d[3])
        : "r"(a[0]), "r"(a[1]), "r"(a[2]), "r"(a[3]), "r"(b[0]), "r"(b[1]));
}

__device__ __forceinline__ void cp_async16(uint32_t smem, const void* gptr) {
    asm volatile("cp.async.cg.shared.global [%0], [%1], 16;" :: "r"(smem), "l"(gptr));
}

// ---------------------------------------------------------------------------
// Pre-conversion kernels.
// ---------------------------------------------------------------------------
__global__ void cvt_tf32_kernel(const float* __restrict__ src,
                                float* __restrict__ dst, int n4) {
    int i = blockIdx.x * blockDim.x + threadIdx.x;
    if (i < n4) {
        float4 v = ((const float4*)src)[i];
        float4 c;
        c.x = f2tff(v.x); c.y = f2tff(v.y); c.z = f2tff(v.z); c.w = f2tff(v.w);
        ((float4*)dst)[i] = c;
    }
}

// src [K][N] row-major -> dst [N][K], tf32-rounded. block (32,8), grid (N/32, K/32).
__global__ void cvt_t_tf32_kernel(const float* __restrict__ src,
                                  float* __restrict__ dst, int K, int N) {
    __shared__ float tile[32][33];
    int nb = blockIdx.x * 32, kb = blockIdx.y * 32;
    int tx = threadIdx.x, ty = threadIdx.y;
    #pragma unroll
    for (int i = 0; i < 32; i += 8)
        tile[ty + i][tx] = f2tff(src[(size_t)(kb + ty + i) * N + nb + tx]);
    __syncthreads();
    #pragma unroll
    for (int i = 0; i < 32; i += 8)
        dst[(size_t)(nb + ty + i) * K + kb + tx] = tile[tx][ty + i];
}

// ---------------------------------------------------------------------------
// tf32 tensor-core GEMM: CTA 128x128x32, 8 warps (2m x 4n), warp 64x32.
// A [M][K] row-major, B pre-TRANSPOSED [N][K]. Both staged via cp.async into
// stride-36 smem; ALL fragments via ldmatrix. One __syncthreads per k-tile.
// ---------------------------------------------------------------------------
#define GBM 128
#define GBN 128
#define GBK 32
#define AS_STRIDE 36
#define BS_STRIDE 36
#define GEMM_BUF (GBM*AS_STRIDE + GBN*BS_STRIDE)      // floats per stage buffer
#define GEMM_SMEM (2 * GEMM_BUF * 4)                  // bytes

__device__ __forceinline__ void gemm_tile_async(const float* __restrict__ A,
                                                const float* __restrict__ Bt,
                                                float (&acc)[4][4][4]) {
    extern __shared__ float smdyn[];

    const int K = DIM;
    const int tid = threadIdx.x;
    const int lane = tid & 31;
    const int w = tid >> 5;
    const int warpM = (w & 1) * 64;
    const int warpN = (w >> 1) * 32;

    const float* Ag  = A  + (size_t)(blockIdx.y * GBM) * K;
    const float* Bgt = Bt + (size_t)(blockIdx.x * GBN) * K;

    const int sub = lane >> 3, r8 = lane & 7;
    // A-frag lane offset (row-major As)
    const uint32_t lofA = (uint32_t)((((sub & 1) * 8 + r8) * AS_STRIDE) * 4 + (sub >> 1) * 16);
    // B-frag lane layout on n-major Bs (validated in attn_tc Ks path)
    const int brow = (sub >> 1) * 8 + r8;
    const int bchunk = (sub & 1) * 16;
    const uint32_t sm_base = (uint32_t)__cvta_generic_to_shared(smdyn);

    const int s_row = tid >> 3;        // 0..31 (+ it*32)
    const int s_k4  = (tid & 7) * 4;

    #define GEMM_STAGE(kt, buf)                                                      \
    {                                                                                \
        uint32_t as = sm_base + (uint32_t)((buf) * GEMM_BUF * 4);                    \
        uint32_t bs = as + (uint32_t)(GBM * AS_STRIDE * 4);                          \
        _Pragma("unroll")                                                            \
        for (int it = 0; it < 4; it++) {                                             \
            cp_async16(as + (uint32_t)(((s_row + it * 32) * AS_STRIDE + s_k4) * 4),  \
                       Ag + (size_t)(s_row + it * 32) * K + (kt) * GBK + s_k4);      \
            cp_async16(bs + (uint32_t)(((s_row + it * 32) * BS_STRIDE + s_k4) * 4),  \
                       Bgt + (size_t)(s_row + it * 32) * K + (kt) * GBK + s_k4);     \
        }                                                                            \
    }

    const int NKT = K / GBK;   // 32
    GEMM_STAGE(0, 0);
    asm volatile("cp.async.commit_group;");

    for (int kt = 0; kt < NKT; kt++) {
        asm volatile("cp.async.wait_group 0;");
        __syncthreads();
        if (kt + 1 < NKT) {
            GEMM_STAGE(kt + 1, (kt + 1) & 1);
            asm volatile("cp.async.commit_group;");
        }

        const uint32_t as_b = sm_base + (uint32_t)((kt & 1) * GEMM_BUF * 4);
        const uint32_t bs_b = as_b + (uint32_t)(GBM * AS_STRIDE * 4);

        #pragma unroll
        for (int ks = 0; ks < 4; ks++) {
            uint32_t af[4][4];
            #pragma unroll
            for (int mt = 0; mt < 4; mt++) {
                uint32_t addr = as_b
                              + (uint32_t)(((warpM + mt * 16) * AS_STRIDE) * 4 + ks * 32)
                              + lofA;
                asm volatile(
                    "ldmatrix.sync.aligned.m8n8.x4.shared.b16 {%0,%1,%2,%3}, [%4];"
                    : "=r"(af[mt][0]), "=r"(af[mt][1]), "=r"(af[mt][2]), "=r"(af[mt][3])
                    : "r"(addr));
            }
            uint32_t bf[4][2];
            #pragma unroll
            for (int p = 0; p < 2; p++) {
                uint32_t bq[4];
                uint32_t baddr = bs_b
                               + (uint32_t)(((warpN + p * 16 + brow) * BS_STRIDE) * 4
                                            + ks * 32 + bchunk);
                asm volatile(
                    "ldmatrix.sync.aligned.m8n8.x4.shared.b16 {%0,%1,%2,%3}, [%4];"
                    : "=r"(bq[0]), "=r"(bq[1]), "=r"(bq[2]), "=r"(bq[3]) : "r"(baddr));
                bf[2 * p][0]     = bq[0];
                bf[2 * p][1]     = bq[1];
                bf[2 * p + 1][0] = bq[2];
                bf[2 * p + 1][1] = bq[3];
            }
            #pragma unroll
            for (int mt = 0; mt < 4; mt++)
                #pragma unroll
                for (int nt = 0; nt < 4; nt++)
                    mma_tf32(acc[mt][nt], af[mt], bf[nt]);
        }
    }
    #undef GEMM_STAGE
}

__global__ __launch_bounds__(256) void gemm_qkv_tc(const float* __restrict__ bias) {
    float acc[4][4][4];
    #pragma unroll
    for (int i = 0; i < 4; i++)
        #pragma unroll
        for (int j = 0; j < 4; j++)
            #pragma unroll
            for (int k = 0; k < 4; k++) acc[i][j][k] = 0.f;

    gemm_tile_async(g_xt, g_wqkvt, acc);

    const int tid = threadIdx.x;
    const int lane = tid & 31;
    const int w = tid >> 5;
    const int warpM = (w & 1) * 64;
    const int warpN = (w >> 1) * 32;
    const int g = lane >> 2, t = lane & 3;

    #pragma unroll
    for (int mt = 0; mt < 4; mt++) {
        #pragma unroll
        for (int nt = 0; nt < 4; nt++) {
            int col = blockIdx.x * GBN + warpN + nt * 8 + t * 2;
            float b0 = bias[col], b1 = bias[col + 1];
            int part = col >> 10;
            int h = (col >> 6) & (NH - 1);
            int d = col & (HD - 1);
            #pragma unroll
            for (int half = 0; half < 2; half++) {
                int r = blockIdx.y * GBM + warpM + mt * 16 + g + half * 8;
                int b_ = r >> 11, s = r & (SEQ - 1);
                float v0 = acc[mt][nt][half * 2 + 0] + b0;
                float v1 = acc[mt][nt][half * 2 + 1] + b1;
                if (part == 0) {
                    int idx = (((b_ * NH + h) * SEQ) + s) * HD + d;
                    g_q[idx]     = f2tff(v0 * 0.125f);
                    g_q[idx + 1] = f2tff(v1 * 0.125f);
                } else if (part == 1) {
                    int idx = (((b_ * NH + h) * SEQ) + s) * HD + d;
                    g_k[idx]     = f2tff(v0);
                    g_k[idx + 1] = f2tff(v1);
                } else {
                    size_t vb = ((size_t)(b_ * NH + h) * HD + d) * SEQ + s;
                    g_vt[vb]       = f2tff(v0);
                    g_vt[vb + SEQ] = f2tff(v1);
                }
            }
        }
    }
}

__global__ __launch_bounds__(256) void gemm_out_tc(const float* __restrict__ bias,
                                                   float* __restrict__ C) {
    float acc[4][4][4];
    #pragma unroll
    for (int i = 0; i < 4; i++)
        #pragma unroll
        for (int j = 0; j < 4; j++)
            #pragma unroll
            for (int k = 0; k < 4; k++) acc[i][j][k] = 0.f;

    gemm_tile_async(g_ao, g_woutt, acc);

    const int tid = threadIdx.x;
    const int lane = tid & 31;
    const int w = tid >> 5;
    const int warpM = (w & 1) * 64;
    const int warpN = (w >> 1) * 32;
    const int g = lane >> 2, t = lane & 3;

    #pragma unroll
    for (int mt = 0; mt < 4; mt++) {
        #pragma unroll
        for (int nt = 0; nt < 4; nt++) {
            int col = blockIdx.x * GBN + warpN + nt * 8 + t * 2;
            float b0 = bias[col], b1 = bias[col + 1];
            #pragma unroll
            for (int half = 0; half < 2; half++) {
                int r = blockIdx.y * GBM + warpM + mt * 16 + g + half * 8;
                float2 o;
                o.x = acc[mt][nt][half * 2 + 0] + b0;
                o.y = acc[mt][nt][half * 2 + 1] + b1;
                *(float2*)(C + (size_t)r * DIM + col) = o;
            }
        }
    }
}

// ---------------------------------------------------------------------------
// Tensor-core causal flash attention (tf32 mma) — unchanged from R7.
// ---------------------------------------------------------------------------
#define ATQ 128
#define ATK 64
#define QS_S 68
#define KS_S 68
#define VT_S 68
#define ATTN_BUF (ATK*KS_S + HD*VT_S)
#define ATTN_SMEM ((ATQ*QS_S + 2*ATTN_BUF) * 4)

__global__ __launch_bounds__(256, 2) void attn_tc() {
    extern __shared__ float sm[];
    float* Qs = sm;

    const int tid = threadIdx.x;
    const int lane = tid & 31;
    const int wp = tid >> 5;
    const int g = lane >> 2, t = lane & 3;

    const int qt = (gridDim.x - 1) - blockIdx.x;
    const int bh = blockIdx.y;
    const int q0 = qt * ATQ;
    const float* Qp  = g_q  + (size_t)bh * SEQ * HD;
    const float* Kp  = g_k  + (size_t)bh * SEQ * HD;
    const float* Vtp = g_vt + (size_t)bh * HD * SEQ;

    const int sub = lane >> 3, r8 = lane & 7;
    const uint32_t lofQ = (uint32_t)((((sub & 1) * 8 + r8) * QS_S) * 4 + (sub >> 1) * 16);
    const int brow = (sub >> 1) * 8 + r8;
    const int bchunk = (sub & 1) * 16;
    const uint32_t qs_base = (uint32_t)__cvta_generic_to_shared(Qs);
    const uint32_t kv_base0 = qs_base + (uint32_t)(ATQ * QS_S * 4);

    const int st_r  = tid >> 4;
    const int st_c4 = (tid & 15) * 4;

    #define ATTN_STAGE(jt, buf)                                                       \
    {                                                                                 \
        uint32_t ksb = kv_base0 + (uint32_t)((buf) * ATTN_BUF * 4);                   \
        uint32_t vtb = ksb + (uint32_t)(ATK * KS_S * 4);                              \
        int kv0_ = (jt) * ATK;                                                        \
        _Pragma("unroll")                                                             \
        for (int it = 0; it < 4; it++) {                                              \
            int r = st_r + it * 16;                                                   \
            cp_async16(ksb + (uint32_t)((r * KS_S + st_c4) * 4),                      \
                       Kp + (size_t)(kv0_ + r) * HD + st_c4);                         \
            cp_async16(vtb + (uint32_t)((r * VT_S + st_c4) * 4),                      \
                       Vtp + (size_t)r * SEQ + kv0_ + st_c4);                         \
        }                                                                             \
    }

    for (int i = tid; i < ATQ * (HD / 4); i += 256) {
        int r = i >> 4, c4 = (i & 15) * 4;
        *(float4*)&Qs[r * QS_S + c4] =
            *(const float4*)(Qp + (size_t)(q0 + r) * HD + c4);
    }

    float o[8][4];
    #pragma unroll
    for (int nt = 0; nt < 8; nt++)
        #pragma unroll
        for (int c = 0; c < 4; c++) o[nt][c] = 0.f;
    float m0 = -1e30f, m1 = -1e30f, l0 = 0.f, l1 = 0.f;

    const int srcA = (lane & ~3) | (t >> 1);
    const int srcB = srcA + 2;

    const int ntiles = 2 * qt + 2;
    ATTN_STAGE(0, 0);
    asm volatile("cp.async.commit_group;");

    for (int jt = 0; jt < ntiles; jt++) {
        asm volatile("cp.async.wait_group 0;");
        __syncthreads();
        if (jt + 1 < ntiles) {
            ATTN_STAGE(jt + 1, (jt + 1) & 1);
            asm volatile("cp.async.commit_group;");
        }
        const int kv0 = jt * ATK;
        const uint32_t ks_base = kv_base0 + (uint32_t)((jt & 1) * ATTN_BUF * 4);
        const uint32_t vt_base = ks_base + (uint32_t)(ATK * KS_S * 4);

        float s[8][4];
        #pragma unroll
        for (int nt = 0; nt < 8; nt++)
            #pragma unroll
            for (int c = 0; c < 4; c++) s[nt][c] = 0.f;

        #pragma unroll
        for (int ks = 0; ks < 8; ks++) {
            uint32_t a[4];
            uint32_t addr = qs_base
                          + (uint32_t)(((wp * 16) * QS_S) * 4 + ks * 32) + lofQ;
            asm volatile(
                "ldmatrix.sync.aligned.m8n8.x4.shared.b16 {%0,%1,%2,%3}, [%4];"
                : "=r"(a[0]), "=r"(a[1]), "=r"(a[2]), "=r"(a[3]) : "r"(addr));
            #pragma unroll
            for (int p = 0; p < 4; p++) {
                uint32_t bq[4];
                uint32_t baddr = ks_base
                               + (uint32_t)(((p * 16 + brow) * KS_S) * 4 + ks * 32 + bchunk);
                asm volatile(
                    "ldmatrix.sync.aligned.m8n8.x4.shared.b16 {%0,%1,%2,%3}, [%4];"
                    : "=r"(bq[0]), "=r"(bq[1]), "=r"(bq[2]), "=r"(bq[3]) : "r"(baddr));
                uint32_t b0[2] = {bq[0], bq[1]};
                uint32_t b1[2] = {bq[2], bq[3]};
                mma_tf32(s[2 * p], a, b0);
                mma_tf32(s[2 * p + 1], a, b1);
            }
        }

        if (jt >= 2 * qt) {
            int r0 = q0 + wp * 16 + g, r1 = r0 + 8;
            #pragma unroll
            for (int nt = 0; nt < 8; nt++) {
                int c0 = kv0 + nt * 8 + 2 * t;
                if (c0 > r0)     s[nt][0] = -1e30f;
                if (c0 + 1 > r0) s[nt][1] = -1e30f;
                if (c0 > r1)     s[nt][2] = -1e30f;
                if (c0 + 1 > r1) s[nt][3] = -1e30f;
            }
        }

        float mx0 = -1e30f, mx1 = -1e30f;
        #pragma unroll
        for (int nt = 0; nt < 8; nt++) {
            mx0 = fmaxf(mx0, fmaxf(s[nt][0], s[nt][1]));
            mx1 = fmaxf(mx1, fmaxf(s[nt][2], s[nt][3]));
        }
        mx0 = fmaxf(mx0, __shfl_xor_sync(0xffffffffu, mx0, 1));
        mx0 = fmaxf(mx0, __shfl_xor_sync(0xffffffffu, mx0, 2));
        mx1 = fmaxf(mx1, __shfl_xor_sync(0xffffffffu, mx1, 1));
        mx1 = fmaxf(mx1, __shfl_xor_sync(0xffffffffu, mx1, 2));
        float mn0 = fmaxf(m0, mx0), mn1 = fmaxf(m1, mx1);
        float corr0 = __expf(m0 - mn0), corr1 = __expf(m1 - mn1);
        m0 = mn0; m1 = mn1;
        float sum0 = 0.f, sum1 = 0.f;
        #pragma unroll
        for (int nt = 0; nt < 8; nt++) {
            s[nt][0] = __expf(s[nt][0] - mn0);
            s[nt][1] = __expf(s[nt][1] - mn0);
            s[nt][2] = __expf(s[nt][2] - mn1);
            s[nt][3] = __expf(s[nt][3] - mn1);
            sum0 += s[nt][0] + s[nt][1];
            sum1 += s[nt][2] + s[nt][3];
        }
        l0 = l0 * corr0 + sum0;
        l1 = l1 * corr1 + sum1;
        #pragma unroll
        for (int nt = 0; nt < 8; nt++) {
            o[nt][0] *= corr0; o[nt][1] *= corr0;
            o[nt][2] *= corr1; o[nt][3] *= corr1;
        }

        uint32_t pt[8][4];
        #pragma unroll
        for (int nt = 0; nt < 8; nt++)
            #pragma unroll
            for (int c = 0; c < 4; c++) pt[nt][c] = f2tf(s[nt][c]);

        #pragma unroll
        for (int ks = 0; ks < 8; ks++) {
            uint32_t a[4];
            {
                uint32_t x0 = __shfl_sync(0xffffffffu, pt[ks][0], srcA);
                uint32_t x1 = __shfl_sync(0xffffffffu, pt[ks][1], srcA);
                a[0] = (t & 1) ? x1 : x0;
                uint32_t y0 = __shfl_sync(0xffffffffu, pt[ks][2], srcA);
                uint32_t y1 = __shfl_sync(0xffffffffu, pt[ks][3], srcA);
                a[1] = (t & 1) ? y1 : y0;
                uint32_t z0 = __shfl_sync(0xffffffffu, pt[ks][0], srcB);
                uint32_t z1 = __shfl_sync(0xffffffffu, pt[ks][1], srcB);
                a[2] = (t & 1) ? z1 : z0;
                uint32_t w0 = __shfl_sync(0xffffffffu, pt[ks][2], srcB);
                uint32_t w1 = __shfl_sync(0xffffffffu, pt[ks][3], srcB);
                a[3] = (t & 1) ? w1 : w0;
            }
            #pragma unroll
            for (int p = 0; p < 4; p++) {
                uint32_t bq[4];
                uint32_t baddr = vt_base
                               + (uint32_t)(((p * 16 + brow) * VT_S) * 4 + ks * 32 + bchunk);
                asm volatile(
                    "ldmatrix.sync.aligned.m8n8.x4.shared.b16 {%0,%1,%2,%3}, [%4];"
                    : "=r"(bq[0]), "=r"(bq[1]), "=r"(bq[2]), "=r"(bq[3]) : "r"(baddr));
                uint32_t b0[2] = {bq[0], bq[1]};
                uint32_t b1[2] = {bq[2], bq[3]};
                mma_tf32(o[2 * p], a, b0);
                mma_tf32(o[2 * p + 1], a, b1);
            }
        }
    }
    #undef ATTN_STAGE

    l0 += __shfl_xor_sync(0xffffffffu, l0, 1);
    l0 += __shfl_xor_sync(0xffffffffu, l0, 2);
    l1 += __shfl_xor_sync(0xffffffffu, l1, 1);
    l1 += __shfl_xor_sync(0xffffffffu, l1, 2);
    float inv0 = 1.f / l0, inv1 = 1.f / l1;

    int b_ = bh >> 4, h = bh & (NH - 1);
    int r0 = q0 + wp * 16 + g, r1 = r0 + 8;
    float* dst0 = g_ao + ((size_t)b_ * SEQ + r0) * DIM + h * HD;
    float* dst1 = g_ao + ((size_t)b_ * SEQ + r1) * DIM + h * HD;
    #pragma unroll
    for (int nt = 0; nt < 8; nt++) {
        int cc = nt * 8 + 2 * t;
        float2 o0, o1;
        o0.x = f2tff(o[nt][0] * inv0); o0.y = f2tff(o[nt][1] * inv0);
        o1.x = f2tff(o[nt][2] * inv1); o1.y = f2tff(o[nt][3] * inv1);
        *(float2*)(dst0 + cc) = o0;
        *(float2*)(dst1 + cc) = o1;
    }
}

// ---------------------------------------------------------------------------
extern "C" void kernel_launch(void* const* d_in, const int* in_sizes, int n_in,
                              void* d_out, int out_size) {
    const float* x     = (const float*)d_in[0];
    const float* W_qkv = (const float*)d_in[1];
    const float* b_qkv = (const float*)d_in[2];
    const float* W_out = (const float*)d_in[3];
    const float* b_out = (const float*)d_in[4];
    float* out = (float*)d_out;

    static float* p_xt = nullptr;
    static float* p_wqkvt = nullptr;
    static float* p_woutt = nullptr;
    if (!p_xt) {
        cudaGetSymbolAddress((void**)&p_xt, g_xt);
        cudaGetSymbolAddress((void**)&p_wqkvt, g_wqkvt);
        cudaGetSymbolAddress((void**)&p_woutt, g_woutt);
        cudaFuncSetAttribute(attn_tc, cudaFuncAttributeMaxDynamicSharedMemorySize, ATTN_SMEM);
        cudaFuncSetAttribute(gemm_qkv_tc, cudaFuncAttributeMaxDynamicSharedMemorySize, GEMM_SMEM);
        cudaFuncSetAttribute(gemm_out_tc, cudaFuncAttributeMaxDynamicSharedMemorySize, GEMM_SMEM);
    }

    cvt_tf32_kernel<<<(MROWS*DIM/4 + 255)/256, 256>>>(x, p_xt, MROWS*DIM/4);
    cvt_t_tf32_kernel<<<dim3(QKV_N/32, DIM/32), dim3(32, 8)>>>(W_qkv, p_wqkvt, DIM, QKV_N);
    cvt_t_tf32_kernel<<<dim3(DIM/32, DIM/32), dim3(32, 8)>>>(W_out, p_woutt, DIM, DIM);

    gemm_qkv_tc<<<dim3(QKV_N / GBN, MROWS / GBM), 256, GEMM_SMEM>>>(b_qkv);
    attn_tc<<<dim3(SEQ / ATQ, BATCH * NH), 256, ATTN_SMEM>>>();
    gemm_out_tc<<<dim3(DIM / GBN, MROWS / GBM), 256, GEMM_SMEM>>>(b_out, out);
}

// round 10
// speedup vs baseline: 2.7864x; 1.7725x over previous
#include <cuda_runtime.h>
#include <cuda_fp16.h>
#include <cstdint>

// Problem constants
#define BATCH 2
#define SEQ   2048
#define DIM   1024
#define NH    16
#define HD    64
#define MROWS (BATCH*SEQ)          // 4096
#define QKV_N (3*DIM)              // 3072
#define QSC   0.18033688011112042f // 0.125 * log2(e); softmax uses ex2

// Scratch (device globals; no allocation allowed). All fp16.
__device__ __half g_xh[MROWS*DIM];        // x
__device__ __half g_wqkvth[QKV_N*DIM];    // W_qkv^T [n][k]
__device__ __half g_woutth[DIM*DIM];      // W_out^T [n][k]
__device__ __half g_qh[BATCH*NH*SEQ*HD];  // [b][h][s][d], scaled by QSC
__device__ __half g_kh[BATCH*NH*SEQ*HD];  // [b][h][s][d]
__device__ __half g_vth[BATCH*NH*HD*SEQ]; // [b][h][d][s]
__device__ __half g_aoh[BATCH*SEQ*DIM];   // attn out [b][s][h*64+d]

__device__ __forceinline__ void mma_f16(float (&d)[4],
                                        const uint32_t (&a)[4],
                                        const uint32_t (&b)[2]) {
    asm volatile(
        "mma.sync.aligned.m16n8k16.row.col.f32.f16.f16.f32 "
        "{%0,%1,%2,%3}, {%4,%5,%6,%7}, {%8,%9}, {%0,%1,%2,%3};"
        : "+f"(d[0]), "+f"(d[1]), "+f"(d[2]), "+f"(d[3])
        : "r"(a[0]), "r"(a[1]), "r"(a[2]), "r"(a[3]), "r"(b[0]), "r"(b[1]));
}

__device__ __forceinline__ void cp_async16(uint32_t smem, const void* gptr) {
    asm volatile("cp.async.cg.shared.global [%0], [%1], 16;" :: "r"(smem), "l"(gptr));
}

__device__ __forceinline__ uint32_t pack_h2(float x, float y) {
    __half2 h = __floats2half2_rn(x, y);
    return *reinterpret_cast<uint32_t*>(&h);
}

__device__ __forceinline__ float fexp2(float x) {
    float y;
    asm("ex2.approx.ftz.f32 %0, %1;" : "=f"(y) : "f"(x));
    return y;
}

// ---------------------------------------------------------------------------
// Pre-conversion kernels (fp32 -> fp16).
// ---------------------------------------------------------------------------
__global__ void cvt_h_kernel(const float* __restrict__ src,
                             __half* __restrict__ dst, int n8) {
    int i = blockIdx.x * blockDim.x + threadIdx.x;
    if (i < n8) {
        float4 v0 = ((const float4*)src)[2 * i];
        float4 v1 = ((const float4*)src)[2 * i + 1];
        uint4 o;
        o.x = pack_h2(v0.x, v0.y);
        o.y = pack_h2(v0.z, v0.w);
        o.z = pack_h2(v1.x, v1.y);
        o.w = pack_h2(v1.z, v1.w);
        ((uint4*)dst)[i] = o;
    }
}

// src [K][N] fp32 -> dst [N][K] fp16. block (32,8), grid (N/32, K/32).
__global__ void cvt_t_h_kernel(const float* __restrict__ src,
                               __half* __restrict__ dst, int K, int N) {
    __shared__ float tile[32][33];
    int nb = blockIdx.x * 32, kb = blockIdx.y * 32;
    int tx = threadIdx.x, ty = threadIdx.y;
    #pragma unroll
    for (int i = 0; i < 32; i += 8)
        tile[ty + i][tx] = src[(size_t)(kb + ty + i) * N + nb + tx];
    __syncthreads();
    #pragma unroll
    for (int i = 0; i < 32; i += 8)
        dst[(size_t)(nb + ty + i) * K + kb + tx] = __float2half_rn(tile[tx][ty + i]);
}

// ---------------------------------------------------------------------------
// fp16 tensor-core GEMM: CTA 128x128, k-tile 32 halves (2 x k16 mma).
// 8 warps (2m x 4n), warp 64x32. A [M][K], B pre-transposed [N][K].
// cp.async double buffer, one __syncthreads per k-tile. All frags ldmatrix.
// smem rows stride 40 halves (80B -> conflict-free ldmatrix at 20-bank step).
// ---------------------------------------------------------------------------
#define AS_HB 80u                      // bytes per smem row (40 halves)
#define GEMM_ABUF 10240u               // 128 rows * 80 B
#define GEMM_BUFB 20480u               // A + B per stage
#define GEMM_SMEMH (2 * 20480 + 256)

__device__ __forceinline__ void gemm_tile_h(const __half* __restrict__ Abase,
                                            const __half* __restrict__ Btbase,
                                            float (&acc)[4][4][4]) {
    extern __shared__ __half smh[];
    const int K = DIM;
    const int tid = threadIdx.x;
    const int lane = tid & 31;
    const int w = tid >> 5;
    const int warpM = (w & 1) * 64;
    const int warpN = (w >> 1) * 32;

    const __half* Ag  = Abase  + (size_t)(blockIdx.y * 128) * K;
    const __half* Bgt = Btbase + (size_t)(blockIdx.x * 128) * K;

    const int sub = lane >> 3, r8 = lane & 7;
    // A frag: r0=(m0-7,k0-7) r1=(m8-15,k0-7) r2=(m0-7,k8-15) r3=(m8-15,k8-15)
    const uint32_t lofA = (uint32_t)(((sub & 1) * 8 + r8) * AS_HB + (sub >> 1) * 16);
    // B frag: r0=(n0-7,k0-7) r1=(n0-7,k8-15) r2=(n8-15,k0-7) r3=(n8-15,k8-15)
    const uint32_t lofB = (uint32_t)(((sub >> 1) * 8 + r8) * AS_HB + (sub & 1) * 16);
    const uint32_t smb = (uint32_t)__cvta_generic_to_shared(smh);

    const int s_row = tid >> 2;        // 0..63 (+64)
    const int s_c   = tid & 3;         // 16B chunk (8 halves)

#define HSTAGE(kt, buf) { \
    uint32_t ab = smb + (uint32_t)(buf) * GEMM_BUFB; \
    uint32_t bb = ab + GEMM_ABUF; \
    _Pragma("unroll") \
    for (int it = 0; it < 2; it++) { \
        int row = s_row + it * 64; \
        cp_async16(ab + (uint32_t)(row * AS_HB + s_c * 16), \
                   Ag + (size_t)row * K + (kt) * 32 + s_c * 8); \
        cp_async16(bb + (uint32_t)(row * AS_HB + s_c * 16), \
                   Bgt + (size_t)row * K + (kt) * 32 + s_c * 8); \
    } \
    asm volatile("cp.async.commit_group;"); }

    const int NKT = K / 32;   // 32
    HSTAGE(0, 0);
    for (int kt = 0; kt < NKT; kt++) {
        asm volatile("cp.async.wait_group 0;");
        __syncthreads();
        if (kt + 1 < NKT) HSTAGE(kt + 1, (kt + 1) & 1);

        const uint32_t ab = smb + (uint32_t)(kt & 1) * GEMM_BUFB;
        const uint32_t bb = ab + GEMM_ABUF;

        #pragma unroll
        for (int ks = 0; ks < 2; ks++) {
            uint32_t af[4][4];
            #pragma unroll
            for (int mt = 0; mt < 4; mt++) {
                uint32_t addr = ab + (uint32_t)((warpM + mt * 16) * AS_HB + ks * 32) + lofA;
                asm volatile(
                    "ldmatrix.sync.aligned.m8n8.x4.shared.b16 {%0,%1,%2,%3}, [%4];"
                    : "=r"(af[mt][0]), "=r"(af[mt][1]), "=r"(af[mt][2]), "=r"(af[mt][3])
                    : "r"(addr));
            }
            uint32_t bf[4][2];
            #pragma unroll
            for (int p = 0; p < 2; p++) {
                uint32_t bq[4];
                uint32_t baddr = bb + (uint32_t)((warpN + p * 16) * AS_HB + ks * 32) + lofB;
                asm volatile(
                    "ldmatrix.sync.aligned.m8n8.x4.shared.b16 {%0,%1,%2,%3}, [%4];"
                    : "=r"(bq[0]), "=r"(bq[1]), "=r"(bq[2]), "=r"(bq[3]) : "r"(baddr));
                bf[2 * p][0]     = bq[0];
                bf[2 * p][1]     = bq[1];
                bf[2 * p + 1][0] = bq[2];
                bf[2 * p + 1][1] = bq[3];
            }
            #pragma unroll
            for (int mt = 0; mt < 4; mt++)
                #pragma unroll
                for (int nt = 0; nt < 4; nt++)
                    mma_f16(acc[mt][nt], af[mt], bf[nt]);
        }
    }
#undef HSTAGE
}

__global__ __launch_bounds__(256) void gemm_qkv_h(const float* __restrict__ bias) {
    float acc[4][4][4];
    #pragma unroll
    for (int i = 0; i < 4; i++)
        #pragma unroll
        for (int j = 0; j < 4; j++)
            #pragma unroll
            for (int k = 0; k < 4; k++) acc[i][j][k] = 0.f;

    gemm_tile_h(g_xh, g_wqkvth, acc);

    const int tid = threadIdx.x;
    const int lane = tid & 31;
    const int w = tid >> 5;
    const int warpM = (w & 1) * 64;
    const int warpN = (w >> 1) * 32;
    const int g = lane >> 2, t = lane & 3;

    #pragma unroll
    for (int mt = 0; mt < 4; mt++) {
        #pragma unroll
        for (int nt = 0; nt < 4; nt++) {
            int col = blockIdx.x * 128 + warpN + nt * 8 + t * 2;
            float b0 = bias[col], b1 = bias[col + 1];
            int part = col >> 10;
            int h = (col >> 6) & (NH - 1);
            int d = col & (HD - 1);
            #pragma unroll
            for (int half = 0; half < 2; half++) {
                int r = blockIdx.y * 128 + warpM + mt * 16 + g + half * 8;
                int b_ = r >> 11, s = r & (SEQ - 1);
                float v0 = acc[mt][nt][half * 2 + 0] + b0;
                float v1 = acc[mt][nt][half * 2 + 1] + b1;
                if (part == 0) {
                    __half2* dst = (__half2*)(g_qh + ((size_t)(b_ * NH + h) * SEQ + s) * HD + d);
                    *dst = __floats2half2_rn(v0 * QSC, v1 * QSC);
                } else if (part == 1) {
                    __half2* dst = (__half2*)(g_kh + ((size_t)(b_ * NH + h) * SEQ + s) * HD + d);
                    *dst = __floats2half2_rn(v0, v1);
                } else {
                    size_t vb = ((size_t)(b_ * NH + h) * HD + d) * SEQ + s;
                    g_vth[vb]       = __float2half_rn(v0);
                    g_vth[vb + SEQ] = __float2half_rn(v1);
                }
            }
        }
    }
}

__global__ __launch_bounds__(256) void gemm_out_h(const float* __restrict__ bias,
                                                  float* __restrict__ C) {
    float acc[4][4][4];
    #pragma unroll
    for (int i = 0; i < 4; i++)
        #pragma unroll
        for (int j = 0; j < 4; j++)
            #pragma unroll
            for (int k = 0; k < 4; k++) acc[i][j][k] = 0.f;

    gemm_tile_h(g_aoh, g_woutth, acc);

    const int tid = threadIdx.x;
    const int lane = tid & 31;
    const int w = tid >> 5;
    const int warpM = (w & 1) * 64;
    const int warpN = (w >> 1) * 32;
    const int g = lane >> 2, t = lane & 3;

    #pragma unroll
    for (int mt = 0; mt < 4; mt++) {
        #pragma unroll
        for (int nt = 0; nt < 4; nt++) {
            int col = blockIdx.x * 128 + warpN + nt * 8 + t * 2;
            float b0 = bias[col], b1 = bias[col + 1];
            #pragma unroll
            for (int half = 0; half < 2; half++) {
                int r = blockIdx.y * 128 + warpM + mt * 16 + g + half * 8;
                float2 o;
                o.x = acc[mt][nt][half * 2 + 0] + b0;
                o.y = acc[mt][nt][half * 2 + 1] + b1;
                *(float2*)(C + (size_t)r * DIM + col) = o;
            }
        }
    }
}

// ---------------------------------------------------------------------------
// fp16 causal flash attention. CTA: 128 q x 64 kv, 8 warps x 16 q-rows.
// S = QK^T via mma k16; P stays in registers (S-accum frag == PV A-frag);
// PV B-frags via ldmatrix on d-major V^T. cp.async double-buffered K/V.
// ---------------------------------------------------------------------------
#define QS_HB 144u                 // bytes per smem row (72 halves)
#define ATTN_QBY (128 * 144)       // 18432
#define ATTN_KVB (64 * 144)        // 9216 per matrix
#define ATTN_BUFB (2 * ATTN_KVB)   // K + Vt per stage
#define ATTN_SMEMH (ATTN_QBY + 2 * ATTN_BUFB)   // 55296 B

__global__ __launch_bounds__(256, 2) void attn_h() {
    extern __shared__ __half smh[];

    const int tid = threadIdx.x;
    const int lane = tid & 31;
    const int wp = tid >> 5;
    const int g = lane >> 2, t = lane & 3;

    const int qt = (gridDim.x - 1) - blockIdx.x;   // longest first
    const int bh = blockIdx.y;
    const int q0 = qt * 128;
    const __half* Qp  = g_qh  + (size_t)bh * SEQ * HD;
    const __half* Kp  = g_kh  + (size_t)bh * SEQ * HD;
    const __half* Vtp = g_vth + (size_t)bh * HD * SEQ;

    const int sub = lane >> 3, r8 = lane & 7;
    const uint32_t lofQ = (uint32_t)(((sub & 1) * 8 + r8) * QS_HB + (sub >> 1) * 16);
    const uint32_t lofB = (uint32_t)(((sub >> 1) * 8 + r8) * QS_HB + (sub & 1) * 16);
    const uint32_t qsb  = (uint32_t)__cvta_generic_to_shared(smh);
    const uint32_t kvb0 = qsb + ATTN_QBY;

    const int st_r = tid >> 3;     // 0..31 (+32)
    const int st_c = tid & 7;      // 16B chunk

    #define ASTG(jt, buf) { \
        uint32_t ksb = kvb0 + (uint32_t)(buf) * ATTN_BUFB; \
        uint32_t vtb = ksb + ATTN_KVB; \
        int kv0_ = (jt) * 64; \
        _Pragma("unroll") \
        for (int it = 0; it < 2; it++) { \
            int r = st_r + it * 32; \
            cp_async16(ksb + (uint32_t)(r * QS_HB + st_c * 16), \
                       Kp + (size_t)(kv0_ + r) * HD + st_c * 8); \
            cp_async16(vtb + (uint32_t)(r * QS_HB + st_c * 16), \
                       Vtp + (size_t)r * SEQ + kv0_ + st_c * 8); \
        } \
        asm volatile("cp.async.commit_group;"); }

    // Load Q tile (plain 16B copies)
    for (int i = tid; i < 128 * 8; i += 256) {
        int r = i >> 3, c = i & 7;
        *(uint4*)((char*)smh + r * QS_HB + c * 16) =
            *(const uint4*)(Qp + (size_t)(q0 + r) * HD + c * 8);
    }

    float o[8][4];
    #pragma unroll
    for (int nt = 0; nt < 8; nt++)
        #pragma unroll
        for (int c = 0; c < 4; c++) o[nt][c] = 0.f;
    float m0 = -1e30f, m1 = -1e30f, l0 = 0.f, l1 = 0.f;

    const int ntiles = 2 * qt + 2;
    ASTG(0, 0);

    for (int jt = 0; jt < ntiles; jt++) {
        asm volatile("cp.async.wait_group 0;");
        __syncthreads();
        if (jt + 1 < ntiles) ASTG(jt + 1, (jt + 1) & 1);

        const int kv0 = jt * 64;
        const uint32_t ksb = kvb0 + (uint32_t)(jt & 1) * ATTN_BUFB;
        const uint32_t vtb = ksb + ATTN_KVB;

        // ---- S = Q K^T (warp: 16q x 64kv, 4 k16 steps over HD) ----
        float s[8][4];
        #pragma unroll
        for (int nt = 0; nt < 8; nt++)
            #pragma unroll
            for (int c = 0; c < 4; c++) s[nt][c] = 0.f;

        #pragma unroll
        for (int ks = 0; ks < 4; ks++) {
            uint32_t a[4];
            uint32_t addr = qsb + (uint32_t)((wp * 16) * QS_HB + ks * 32) + lofQ;
            asm volatile(
                "ldmatrix.sync.aligned.m8n8.x4.shared.b16 {%0,%1,%2,%3}, [%4];"
                : "=r"(a[0]), "=r"(a[1]), "=r"(a[2]), "=r"(a[3]) : "r"(addr));
            #pragma unroll
            for (int p = 0; p < 4; p++) {
                uint32_t bq[4];
                uint32_t baddr = ksb + (uint32_t)((p * 16) * QS_HB + ks * 32) + lofB;
                asm volatile(
                    "ldmatrix.sync.aligned.m8n8.x4.shared.b16 {%0,%1,%2,%3}, [%4];"
                    : "=r"(bq[0]), "=r"(bq[1]), "=r"(bq[2]), "=r"(bq[3]) : "r"(baddr));
                uint32_t b0[2] = {bq[0], bq[1]};
                uint32_t b1[2] = {bq[2], bq[3]};
                mma_f16(s[2 * p], a, b0);
                mma_f16(s[2 * p + 1], a, b1);
            }
        }

        // Causal mask on the two diagonal tiles
        if (jt >= 2 * qt) {
            int r0 = q0 + wp * 16 + g, r1 = r0 + 8;
            #pragma unroll
            for (int nt = 0; nt < 8; nt++) {
                int c0 = kv0 + nt * 8 + 2 * t;
                if (c0 > r0)     s[nt][0] = -1e30f;
                if (c0 + 1 > r0) s[nt][1] = -1e30f;
                if (c0 > r1)     s[nt][2] = -1e30f;
                if (c0 + 1 > r1) s[nt][3] = -1e30f;
            }
        }

        // ---- Online softmax in exp2 domain (log2e folded into Q) ----
        float mx0 = -1e30f, mx1 = -1e30f;
        #pragma unroll
        for (int nt = 0; nt < 8; nt++) {
            mx0 = fmaxf(mx0, fmaxf(s[nt][0], s[nt][1]));
            mx1 = fmaxf(mx1, fmaxf(s[nt][2], s[nt][3]));
        }
        mx0 = fmaxf(mx0, __shfl_xor_sync(0xffffffffu, mx0, 1));
        mx0 = fmaxf(mx0, __shfl_xor_sync(0xffffffffu, mx0, 2));
        mx1 = fmaxf(mx1, __shfl_xor_sync(0xffffffffu, mx1, 1));
        mx1 = fmaxf(mx1, __shfl_xor_sync(0xffffffffu, mx1, 2));
        float mn0 = fmaxf(m0, mx0), mn1 = fmaxf(m1, mx1);
        float corr0 = fexp2(m0 - mn0), corr1 = fexp2(m1 - mn1);
        m0 = mn0; m1 = mn1;
        float sum0 = 0.f, sum1 = 0.f;
        #pragma unroll
        for (int nt = 0; nt < 8; nt++) {
            s[nt][0] = fexp2(s[nt][0] - mn0);
            s[nt][1] = fexp2(s[nt][1] - mn0);
            s[nt][2] = fexp2(s[nt][2] - mn1);
            s[nt][3] = fexp2(s[nt][3] - mn1);
            sum0 += s[nt][0] + s[nt][1];
            sum1 += s[nt][2] + s[nt][3];
        }
        l0 = l0 * corr0 + sum0;
        l1 = l1 * corr1 + sum1;
        #pragma unroll
        for (int nt = 0; nt < 8; nt++) {
            o[nt][0] *= corr0; o[nt][1] *= corr0;
            o[nt][2] *= corr1; o[nt][3] *= corr1;
        }

        // ---- O += P V : A-frags packed directly from S accumulators ----
        #pragma unroll
        for (int ks = 0; ks < 4; ks++) {
            uint32_t a[4];
            a[0] = pack_h2(s[2 * ks][0],     s[2 * ks][1]);
            a[1] = pack_h2(s[2 * ks][2],     s[2 * ks][3]);
            a[2] = pack_h2(s[2 * ks + 1][0], s[2 * ks + 1][1]);
            a[3] = pack_h2(s[2 * ks + 1][2], s[2 * ks + 1][3]);
            #pragma unroll
            for (int p = 0; p < 4; p++) {
                uint32_t bq[4];
                uint32_t baddr = vtb + (uint32_t)((p * 16) * QS_HB + ks * 32) + lofB;
                asm volatile(
                    "ldmatrix.sync.aligned.m8n8.x4.shared.b16 {%0,%1,%2,%3}, [%4];"
                    : "=r"(bq[0]), "=r"(bq[1]), "=r"(bq[2]), "=r"(bq[3]) : "r"(baddr));
                uint32_t b0[2] = {bq[0], bq[1]};
                uint32_t b1[2] = {bq[2], bq[3]};
                mma_f16(o[2 * p], a, b0);
                mma_f16(o[2 * p + 1], a, b1);
            }
        }
    }
    #undef ASTG

    l0 += __shfl_xor_sync(0xffffffffu, l0, 1);
    l0 += __shfl_xor_sync(0xffffffffu, l0, 2);
    l1 += __shfl_xor_sync(0xffffffffu, l1, 1);
    l1 += __shfl_xor_sync(0xffffffffu, l1, 2);
    float inv0 = 1.f / l0, inv1 = 1.f / l1;

    int b_ = bh >> 4, h = bh & (NH - 1);
    int r0 = q0 + wp * 16 + g, r1 = r0 + 8;
    __half* dst0 = g_aoh + ((size_t)b_ * SEQ + r0) * DIM + h * HD;
    __half* dst1 = g_aoh + ((size_t)b_ * SEQ + r1) * DIM + h * HD;
    #pragma unroll
    for (int nt = 0; nt < 8; nt++) {
        int cc = nt * 8 + 2 * t;
        *(__half2*)(dst0 + cc) = __floats2half2_rn(o[nt][0] * inv0, o[nt][1] * inv0);
        *(__half2*)(dst1 + cc) = __floats2half2_rn(o[nt][2] * inv1, o[nt][3] * inv1);
    }
}

// ---------------------------------------------------------------------------
extern "C" void kernel_launch(void* const* d_in, const int* in_sizes, int n_in,
                              void* d_out, int out_size) {
    const float* x     = (const float*)d_in[0];
    const float* W_qkv = (const float*)d_in[1];
    const float* b_qkv = (const float*)d_in[2];
    const float* W_out = (const float*)d_in[3];
    const float* b_out = (const float*)d_in[4];
    float* out = (float*)d_out;

    static __half* p_xh = nullptr;
    static __half* p_wqkvth = nullptr;
    static __half* p_woutth = nullptr;
    if (!p_xh) {
        cudaGetSymbolAddress((void**)&p_xh, g_xh);
        cudaGetSymbolAddress((void**)&p_wqkvth, g_wqkvth);
        cudaGetSymbolAddress((void**)&p_woutth, g_woutth);
        cudaFuncSetAttribute(attn_h, cudaFuncAttributeMaxDynamicSharedMemorySize, ATTN_SMEMH);
        cudaFuncSetAttribute(gemm_qkv_h, cudaFuncAttributeMaxDynamicSharedMemorySize, GEMM_SMEMH);
        cudaFuncSetAttribute(gemm_out_h, cudaFuncAttributeMaxDynamicSharedMemorySize, GEMM_SMEMH);
    }

    cvt_h_kernel<<<(MROWS*DIM/8 + 255)/256, 256>>>(x, p_xh, MROWS*DIM/8);
    cvt_t_h_kernel<<<dim3(QKV_N/32, DIM/32), dim3(32, 8)>>>(W_qkv, p_wqkvth, DIM, QKV_N);
    cvt_t_h_kernel<<<dim3(DIM/32, DIM/32), dim3(32, 8)>>>(W_out, p_woutth, DIM, DIM);

    gemm_qkv_h<<<dim3(QKV_N / 128, MROWS / 128), 256, GEMM_SMEMH>>>(b_qkv);
    attn_h<<<dim3(SEQ / 128, BATCH * NH), 256, ATTN_SMEMH>>>();
    gemm_out_h<<<dim3(DIM / 128, MROWS / 128), 256, GEMM_SMEMH>>>(b_out, out);
}

// round 11
// speedup vs baseline: 3.0151x; 1.0821x over previous
#include <cuda_runtime.h>
#include <cuda_fp16.h>
#include <cstdint>

// Problem constants
#define BATCH 2
#define SEQ   2048
#define DIM   1024
#define NH    16
#define HD    64
#define MROWS (BATCH*SEQ)          // 4096
#define QKV_N (3*DIM)              // 3072
#define QSC   0.18033688011112042f // 0.125 * log2(e); softmax uses ex2

// Scratch (device globals; no allocation allowed). All fp16.
__device__ __half g_xh[MROWS*DIM];        // x
__device__ __half g_wqkvth[QKV_N*DIM];    // W_qkv^T [n][k]
__device__ __half g_woutth[DIM*DIM];      // W_out^T [n][k]
__device__ __half g_qh[BATCH*NH*SEQ*HD];  // [b][h][s][d], scaled by QSC
__device__ __half g_kh[BATCH*NH*SEQ*HD];  // [b][h][s][d]
__device__ __half g_vth[BATCH*NH*HD*SEQ]; // [b][h][d][s]
__device__ __half g_aoh[BATCH*SEQ*DIM];   // attn out [b][s][h*64+d]

__device__ __forceinline__ void mma_f16(float (&d)[4],
                                        const uint32_t (&a)[4],
                                        const uint32_t (&b)[2]) {
    asm volatile(
        "mma.sync.aligned.m16n8k16.row.col.f32.f16.f16.f32 "
        "{%0,%1,%2,%3}, {%4,%5,%6,%7}, {%8,%9}, {%0,%1,%2,%3};"
        : "+f"(d[0]), "+f"(d[1]), "+f"(d[2]), "+f"(d[3])
        : "r"(a[0]), "r"(a[1]), "r"(a[2]), "r"(a[3]), "r"(b[0]), "r"(b[1]));
}

__device__ __forceinline__ void cp_async16(uint32_t smem, const void* gptr) {
    asm volatile("cp.async.cg.shared.global [%0], [%1], 16;" :: "r"(smem), "l"(gptr));
}

__device__ __forceinline__ uint32_t pack_h2(float x, float y) {
    __half2 h = __floats2half2_rn(x, y);
    return *reinterpret_cast<uint32_t*>(&h);
}

__device__ __forceinline__ float fexp2(float x) {
    float y;
    asm("ex2.approx.ftz.f32 %0, %1;" : "=f"(y) : "f"(x));
    return y;
}

// ---------------------------------------------------------------------------
// Pre-conversion kernels (fp32 -> fp16).
// ---------------------------------------------------------------------------
__global__ void cvt_h_kernel(const float* __restrict__ src,
                             __half* __restrict__ dst, int n8) {
    int i = blockIdx.x * blockDim.x + threadIdx.x;
    if (i < n8) {
        float4 v0 = ((const float4*)src)[2 * i];
        float4 v1 = ((const float4*)src)[2 * i + 1];
        uint4 o;
        o.x = pack_h2(v0.x, v0.y);
        o.y = pack_h2(v0.z, v0.w);
        o.z = pack_h2(v1.x, v1.y);
        o.w = pack_h2(v1.z, v1.w);
        ((uint4*)dst)[i] = o;
    }
}

__global__ void cvt_t_h_kernel(const float* __restrict__ src,
                               __half* __restrict__ dst, int K, int N) {
    __shared__ float tile[32][33];
    int nb = blockIdx.x * 32, kb = blockIdx.y * 32;
    int tx = threadIdx.x, ty = threadIdx.y;
    #pragma unroll
    for (int i = 0; i < 32; i += 8)
        tile[ty + i][tx] = src[(size_t)(kb + ty + i) * N + nb + tx];
    __syncthreads();
    #pragma unroll
    for (int i = 0; i < 32; i += 8)
        dst[(size_t)(nb + ty + i) * K + kb + tx] = __float2half_rn(tile[tx][ty + i]);
}

// ---------------------------------------------------------------------------
// fp16 tensor-core GEMM: CTA 128x128, k-tile 64 halves (4 x k16 mma steps).
// 8 warps (2m x 4n), warp 64x32. A [M][K], B pre-transposed [N][K].
// cp.async double buffer, ONE __syncthreads per 64-deep k-tile (16 total).
// smem rows: 64 halves + 8 pad = 144 B stride (conflict-free, == attn QS_HB).
// ---------------------------------------------------------------------------
#define AS_HB 144u                     // bytes per smem row (72 halves)
#define GEMM_ABUF 18432u               // 128 rows * 144 B
#define GEMM_BUFB 36864u               // A + B per stage
#define GEMM_SMEMH (2 * 36864 + 256)

__device__ __forceinline__ void gemm_tile_h(const __half* __restrict__ Abase,
                                            const __half* __restrict__ Btbase,
                                            float (&acc)[4][4][4]) {
    extern __shared__ __half smh[];
    const int K = DIM;
    const int tid = threadIdx.x;
    const int lane = tid & 31;
    const int w = tid >> 5;
    const int warpM = (w & 1) * 64;
    const int warpN = (w >> 1) * 32;

    const __half* Ag  = Abase  + (size_t)(blockIdx.y * 128) * K;
    const __half* Bgt = Btbase + (size_t)(blockIdx.x * 128) * K;

    const int sub = lane >> 3, r8 = lane & 7;
    const uint32_t lofA = (uint32_t)(((sub & 1) * 8 + r8) * AS_HB + (sub >> 1) * 16);
    const uint32_t lofB = (uint32_t)(((sub >> 1) * 8 + r8) * AS_HB + (sub & 1) * 16);
    const uint32_t smb = (uint32_t)__cvta_generic_to_shared(smh);

    const int s_row = tid >> 3;        // 0..31 (+32 per it)
    const int s_c   = tid & 7;         // 16B chunk (8 halves), 8 chunks = 64 halves

#define HSTAGE(kt, buf) { \
    uint32_t ab = smb + (uint32_t)(buf) * GEMM_BUFB; \
    uint32_t bb = ab + GEMM_ABUF; \
    _Pragma("unroll") \
    for (int it = 0; it < 4; it++) { \
        int row = s_row + it * 32; \
        cp_async16(ab + (uint32_t)(row * AS_HB + s_c * 16), \
                   Ag + (size_t)row * K + (kt) * 64 + s_c * 8); \
        cp_async16(bb + (uint32_t)(row * AS_HB + s_c * 16), \
                   Bgt + (size_t)row * K + (kt) * 64 + s_c * 8); \
    } \
    asm volatile("cp.async.commit_group;"); }

    const int NKT = K / 64;   // 16
    HSTAGE(0, 0);
    for (int kt = 0; kt < NKT; kt++) {
        asm volatile("cp.async.wait_group 0;");
        __syncthreads();
        if (kt + 1 < NKT) HSTAGE(kt + 1, (kt + 1) & 1);

        const uint32_t ab = smb + (uint32_t)(kt & 1) * GEMM_BUFB;
        const uint32_t bb = ab + GEMM_ABUF;

        #pragma unroll
        for (int ks = 0; ks < 4; ks++) {
            uint32_t af[4][4];
            #pragma unroll
            for (int mt = 0; mt < 4; mt++) {
                uint32_t addr = ab + (uint32_t)((warpM + mt * 16) * AS_HB + ks * 32) + lofA;
                asm volatile(
                    "ldmatrix.sync.aligned.m8n8.x4.shared.b16 {%0,%1,%2,%3}, [%4];"
                    : "=r"(af[mt][0]), "=r"(af[mt][1]), "=r"(af[mt][2]), "=r"(af[mt][3])
                    : "r"(addr));
            }
            uint32_t bf[4][2];
            #pragma unroll
            for (int p = 0; p < 2; p++) {
                uint32_t bq[4];
                uint32_t baddr = bb + (uint32_t)((warpN + p * 16) * AS_HB + ks * 32) + lofB;
                asm volatile(
                    "ldmatrix.sync.aligned.m8n8.x4.shared.b16 {%0,%1,%2,%3}, [%4];"
                    : "=r"(bq[0]), "=r"(bq[1]), "=r"(bq[2]), "=r"(bq[3]) : "r"(baddr));
                bf[2 * p][0]     = bq[0];
                bf[2 * p][1]     = bq[1];
                bf[2 * p + 1][0] = bq[2];
                bf[2 * p + 1][1] = bq[3];
            }
            #pragma unroll
            for (int mt = 0; mt < 4; mt++)
                #pragma unroll
                for (int nt = 0; nt < 4; nt++)
                    mma_f16(acc[mt][nt], af[mt], bf[nt]);
        }
    }
#undef HSTAGE
}

__global__ __launch_bounds__(256) void gemm_qkv_h(const float* __restrict__ bias) {
    float acc[4][4][4];
    #pragma unroll
    for (int i = 0; i < 4; i++)
        #pragma unroll
        for (int j = 0; j < 4; j++)
            #pragma unroll
            for (int k = 0; k < 4; k++) acc[i][j][k] = 0.f;

    gemm_tile_h(g_xh, g_wqkvth, acc);

    const int tid = threadIdx.x;
    const int lane = tid & 31;
    const int w = tid >> 5;
    const int warpM = (w & 1) * 64;
    const int warpN = (w >> 1) * 32;
    const int g = lane >> 2, t = lane & 3;

    #pragma unroll
    for (int mt = 0; mt < 4; mt++) {
        #pragma unroll
        for (int nt = 0; nt < 4; nt++) {
            int col = blockIdx.x * 128 + warpN + nt * 8 + t * 2;
            float b0 = bias[col], b1 = bias[col + 1];
            int part = col >> 10;
            int h = (col >> 6) & (NH - 1);
            int d = col & (HD - 1);
            #pragma unroll
            for (int half = 0; half < 2; half++) {
                int r = blockIdx.y * 128 + warpM + mt * 16 + g + half * 8;
                int b_ = r >> 11, s = r & (SEQ - 1);
                float v0 = acc[mt][nt][half * 2 + 0] + b0;
                float v1 = acc[mt][nt][half * 2 + 1] + b1;
                if (part == 0) {
                    __half2* dst = (__half2*)(g_qh + ((size_t)(b_ * NH + h) * SEQ + s) * HD + d);
                    *dst = __floats2half2_rn(v0 * QSC, v1 * QSC);
                } else if (part == 1) {
                    __half2* dst = (__half2*)(g_kh + ((size_t)(b_ * NH + h) * SEQ + s) * HD + d);
                    *dst = __floats2half2_rn(v0, v1);
                } else {
                    size_t vb = ((size_t)(b_ * NH + h) * HD + d) * SEQ + s;
                    g_vth[vb]       = __float2half_rn(v0);
                    g_vth[vb + SEQ] = __float2half_rn(v1);
                }
            }
        }
    }
}

__global__ __launch_bounds__(256) void gemm_out_h(const float* __restrict__ bias,
                                                  float* __restrict__ C) {
    float acc[4][4][4];
    #pragma unroll
    for (int i = 0; i < 4; i++)
        #pragma unroll
        for (int j = 0; j < 4; j++)
            #pragma unroll
            for (int k = 0; k < 4; k++) acc[i][j][k] = 0.f;

    gemm_tile_h(g_aoh, g_woutth, acc);

    const int tid = threadIdx.x;
    const int lane = tid & 31;
    const int w = tid >> 5;
    const int warpM = (w & 1) * 64;
    const int warpN = (w >> 1) * 32;
    const int g = lane >> 2, t = lane & 3;

    #pragma unroll
    for (int mt = 0; mt < 4; mt++) {
        #pragma unroll
        for (int nt = 0; nt < 4; nt++) {
            int col = blockIdx.x * 128 + warpN + nt * 8 + t * 2;
            float b0 = bias[col], b1 = bias[col + 1];
            #pragma unroll
            for (int half = 0; half < 2; half++) {
                int r = blockIdx.y * 128 + warpM + mt * 16 + g + half * 8;
                float2 o;
                o.x = acc[mt][nt][half * 2 + 0] + b0;
                o.y = acc[mt][nt][half * 2 + 1] + b1;
                *(float2*)(C + (size_t)r * DIM + col) = o;
            }
        }
    }
}

// ---------------------------------------------------------------------------
// fp16 causal flash attention — unchanged from R10.
// ---------------------------------------------------------------------------
#define QS_HB 144u
#define ATTN_QBY (128 * 144)
#define ATTN_KVB (64 * 144)
#define ATTN_BUFB (2 * ATTN_KVB)
#define ATTN_SMEMH (ATTN_QBY + 2 * ATTN_BUFB)

__global__ __launch_bounds__(256, 2) void attn_h() {
    extern __shared__ __half smh[];

    const int tid = threadIdx.x;
    const int lane = tid & 31;
    const int wp = tid >> 5;
    const int g = lane >> 2, t = lane & 3;

    const int qt = (gridDim.x - 1) - blockIdx.x;
    const int bh = blockIdx.y;
    const int q0 = qt * 128;
    const __half* Qp  = g_qh  + (size_t)bh * SEQ * HD;
    const __half* Kp  = g_kh  + (size_t)bh * SEQ * HD;
    const __half* Vtp = g_vth + (size_t)bh * HD * SEQ;

    const int sub = lane >> 3, r8 = lane & 7;
    const uint32_t lofQ = (uint32_t)(((sub & 1) * 8 + r8) * QS_HB + (sub >> 1) * 16);
    const uint32_t lofB = (uint32_t)(((sub >> 1) * 8 + r8) * QS_HB + (sub & 1) * 16);
    const uint32_t qsb  = (uint32_t)__cvta_generic_to_shared(smh);
    const uint32_t kvb0 = qsb + ATTN_QBY;

    const int st_r = tid >> 3;
    const int st_c = tid & 7;

    #define ASTG(jt, buf) { \
        uint32_t ksb = kvb0 + (uint32_t)(buf) * ATTN_BUFB; \
        uint32_t vtb = ksb + ATTN_KVB; \
        int kv0_ = (jt) * 64; \
        _Pragma("unroll") \
        for (int it = 0; it < 2; it++) { \
            int r = st_r + it * 32; \
            cp_async16(ksb + (uint32_t)(r * QS_HB + st_c * 16), \
                       Kp + (size_t)(kv0_ + r) * HD + st_c * 8); \
            cp_async16(vtb + (uint32_t)(r * QS_HB + st_c * 16), \
                       Vtp + (size_t)r * SEQ + kv0_ + st_c * 8); \
        } \
        asm volatile("cp.async.commit_group;"); }

    for (int i = tid; i < 128 * 8; i += 256) {
        int r = i >> 3, c = i & 7;
        *(uint4*)((char*)smh + r * QS_HB + c * 16) =
            *(const uint4*)(Qp + (size_t)(q0 + r) * HD + c * 8);
    }

    float o[8][4];
    #pragma unroll
    for (int nt = 0; nt < 8; nt++)
        #pragma unroll
        for (int c = 0; c < 4; c++) o[nt][c] = 0.f;
    float m0 = -1e30f, m1 = -1e30f, l0 = 0.f, l1 = 0.f;

    const int ntiles = 2 * qt + 2;
    ASTG(0, 0);

    for (int jt = 0; jt < ntiles; jt++) {
        asm volatile("cp.async.wait_group 0;");
        __syncthreads();
        if (jt + 1 < ntiles) ASTG(jt + 1, (jt + 1) & 1);

        const int kv0 = jt * 64;
        const uint32_t ksb = kvb0 + (uint32_t)(jt & 1) * ATTN_BUFB;
        const uint32_t vtb = ksb + ATTN_KVB;

        float s[8][4];
        #pragma unroll
        for (int nt = 0; nt < 8; nt++)
            #pragma unroll
            for (int c = 0; c < 4; c++) s[nt][c] = 0.f;

        #pragma unroll
        for (int ks = 0; ks < 4; ks++) {
            uint32_t a[4];
            uint32_t addr = qsb + (uint32_t)((wp * 16) * QS_HB + ks * 32) + lofQ;
            asm volatile(
                "ldmatrix.sync.aligned.m8n8.x4.shared.b16 {%0,%1,%2,%3}, [%4];"
                : "=r"(a[0]), "=r"(a[1]), "=r"(a[2]), "=r"(a[3]) : "r"(addr));
            #pragma unroll
            for (int p = 0; p < 4; p++) {
                uint32_t bq[4];
                uint32_t baddr = ksb + (uint32_t)((p * 16) * QS_HB + ks * 32) + lofB;
                asm volatile(
                    "ldmatrix.sync.aligned.m8n8.x4.shared.b16 {%0,%1,%2,%3}, [%4];"
                    : "=r"(bq[0]), "=r"(bq[1]), "=r"(bq[2]), "=r"(bq[3]) : "r"(baddr));
                uint32_t b0[2] = {bq[0], bq[1]};
                uint32_t b1[2] = {bq[2], bq[3]};
                mma_f16(s[2 * p], a, b0);
                mma_f16(s[2 * p + 1], a, b1);
            }
        }

        if (jt >= 2 * qt) {
            int r0 = q0 + wp * 16 + g, r1 = r0 + 8;
            #pragma unroll
            for (int nt = 0; nt < 8; nt++) {
                int c0 = kv0 + nt * 8 + 2 * t;
                if (c0 > r0)     s[nt][0] = -1e30f;
                if (c0 + 1 > r0) s[nt][1] = -1e30f;
                if (c0 > r1)     s[nt][2] = -1e30f;
                if (c0 + 1 > r1) s[nt][3] = -1e30f;
            }
        }

        float mx0 = -1e30f, mx1 = -1e30f;
        #pragma unroll
        for (int nt = 0; nt < 8; nt++) {
            mx0 = fmaxf(mx0, fmaxf(s[nt][0], s[nt][1]));
            mx1 = fmaxf(mx1, fmaxf(s[nt][2], s[nt][3]));
        }
        mx0 = fmaxf(mx0, __shfl_xor_sync(0xffffffffu, mx0, 1));
        mx0 = fmaxf(mx0, __shfl_xor_sync(0xffffffffu, mx0, 2));
        mx1 = fmaxf(mx1, __shfl_xor_sync(0xffffffffu, mx1, 1));
        mx1 = fmaxf(mx1, __shfl_xor_sync(0xffffffffu, mx1, 2));
        float mn0 = fmaxf(m0, mx0), mn1 = fmaxf(m1, mx1);
        float corr0 = fexp2(m0 - mn0), corr1 = fexp2(m1 - mn1);
        m0 = mn0; m1 = mn1;
        float sum0 = 0.f, sum1 = 0.f;
        #pragma unroll
        for (int nt = 0; nt < 8; nt++) {
            s[nt][0] = fexp2(s[nt][0] - mn0);
            s[nt][1] = fexp2(s[nt][1] - mn0);
            s[nt][2] = fexp2(s[nt][2] - mn1);
            s[nt][3] = fexp2(s[nt][3] - mn1);
            sum0 += s[nt][0] + s[nt][1];
            sum1 += s[nt][2] + s[nt][3];
        }
        l0 = l0 * corr0 + sum0;
        l1 = l1 * corr1 + sum1;
        #pragma unroll
        for (int nt = 0; nt < 8; nt++) {
            o[nt][0] *= corr0; o[nt][1] *= corr0;
            o[nt][2] *= corr1; o[nt][3] *= corr1;
        }

        #pragma unroll
        for (int ks = 0; ks < 4; ks++) {
            uint32_t a[4];
            a[0] = pack_h2(s[2 * ks][0],     s[2 * ks][1]);
            a[1] = pack_h2(s[2 * ks][2],     s[2 * ks][3]);
            a[2] = pack_h2(s[2 * ks + 1][0], s[2 * ks + 1][1]);
            a[3] = pack_h2(s[2 * ks + 1][2], s[2 * ks + 1][3]);
            #pragma unroll
            for (int p = 0; p < 4; p++) {
                uint32_t bq[4];
                uint32_t baddr = vtb + (uint32_t)((p * 16) * QS_HB + ks * 32) + lofB;
                asm volatile(
                    "ldmatrix.sync.aligned.m8n8.x4.shared.b16 {%0,%1,%2,%3}, [%4];"
                    : "=r"(bq[0]), "=r"(bq[1]), "=r"(bq[2]), "=r"(bq[3]) : "r"(baddr));
                uint32_t b0[2] = {bq[0], bq[1]};
                uint32_t b1[2] = {bq[2], bq[3]};
                mma_f16(o[2 * p], a, b0);
                mma_f16(o[2 * p + 1], a, b1);
            }
        }
    }
    #undef ASTG

    l0 += __shfl_xor_sync(0xffffffffu, l0, 1);
    l0 += __shfl_xor_sync(0xffffffffu, l0, 2);
    l1 += __shfl_xor_sync(0xffffffffu, l1, 1);
    l1 += __shfl_xor_sync(0xffffffffu, l1, 2);
    float inv0 = 1.f / l0, inv1 = 1.f / l1;

    int b_ = bh >> 4, h = bh & (NH - 1);
    int r0 = q0 + wp * 16 + g, r1 = r0 + 8;
    __half* dst0 = g_aoh + ((size_t)b_ * SEQ + r0) * DIM + h * HD;
    __half* dst1 = g_aoh + ((size_t)b_ * SEQ + r1) * DIM + h * HD;
    #pragma unroll
    for (int nt = 0; nt < 8; nt++) {
        int cc = nt * 8 + 2 * t;
        *(__half2*)(dst0 + cc) = __floats2half2_rn(o[nt][0] * inv0, o[nt][1] * inv0);
        *(__half2*)(dst1 + cc) = __floats2half2_rn(o[nt][2] * inv1, o[nt][3] * inv1);
    }
}

// ---------------------------------------------------------------------------
extern "C" void kernel_launch(void* const* d_in, const int* in_sizes, int n_in,
                              void* d_out, int out_size) {
    const float* x     = (const float*)d_in[0];
    const float* W_qkv = (const float*)d_in[1];
    const float* b_qkv = (const float*)d_in[2];
    const float* W_out = (const float*)d_in[3];
    const float* b_out = (const float*)d_in[4];
    float* out = (float*)d_out;

    static __half* p_xh = nullptr;
    static __half* p_wqkvth = nullptr;
    static __half* p_woutth = nullptr;
    if (!p_xh) {
        cudaGetSymbolAddress((void**)&p_xh, g_xh);
        cudaGetSymbolAddress((void**)&p_wqkvth, g_wqkvth);
        cudaGetSymbolAddress((void**)&p_woutth, g_woutth);
        cudaFuncSetAttribute(attn_h, cudaFuncAttributeMaxDynamicSharedMemorySize, ATTN_SMEMH);
        cudaFuncSetAttribute(gemm_qkv_h, cudaFuncAttributeMaxDynamicSharedMemorySize, GEMM_SMEMH);
        cudaFuncSetAttribute(gemm_out_h, cudaFuncAttributeMaxDynamicSharedMemorySize, GEMM_SMEMH);
    }

    cvt_h_kernel<<<(MROWS*DIM/8 + 255)/256, 256>>>(x, p_xh, MROWS*DIM/8);
    cvt_t_h_kernel<<<dim3(QKV_N/32, DIM/32), dim3(32, 8)>>>(W_qkv, p_wqkvth, DIM, QKV_N);
    cvt_t_h_kernel<<<dim3(DIM/32, DIM/32), dim3(32, 8)>>>(W_out, p_woutth, DIM, DIM);

    gemm_qkv_h<<<dim3(QKV_N / 128, MROWS / 128), 256, GEMM_SMEMH>>>(b_qkv);
    attn_h<<<dim3(SEQ / 128, BATCH * NH), 256, ATTN_SMEMH>>>();
    gemm_out_h<<<dim3(DIM / 128, MROWS / 128), 256, GEMM_SMEMH>>>(b_out, out);
}